// round 2
// baseline (speedup 1.0000x reference)
#include <cuda_runtime.h>
#include <math.h>

#define NB 8
#define NC 256
#define HWF 4096
#define HW4 1024
#define EPSV 1e-5f

// ---------------- scratch (static __device__, no allocation) ----------------
__device__ float g_y1[NB * 32  * HWF];          //  4 MB conv1 pre-pool
__device__ float g_y3[NB * 128 * HWF];          // 16 MB conv3 pre-pool
__device__ float g_f [NB * 32  * HW4];          //  1 MB pooled f  [b][k][n]
__device__ float g_gm[NB * 32  * HWF];          //  4 MB g         [b][k][m]
__device__ float g_hh[NB * 128 * HW4];          //  4 MB pooled hh [b][c][n]
__device__ float g_st[(size_t)NB * HWF * HW4];  // 134 MB scores st[b][m][n]
__device__ float g_o [NB * 128 * HWF];          // 16 MB attention out [b][c][m]

// =====================================================================
// proj: y[b][o][p] = relu( (sum_c w[o][c]*Bmat[b][c][p]) * alpha[o] + beta[o] )
// Bmat row stride HWF. Tiled 64x64, BK=16, 256 threads, 4x4 per thread.
// =====================================================================
__global__ void proj_kernel(const float* __restrict__ Bmat,
                            const float* __restrict__ w,
                            const float* __restrict__ bb, const float* __restrict__ ss,
                            const float* __restrict__ tt, const float* __restrict__ mm,
                            const float* __restrict__ vv,
                            float* __restrict__ y, int M, int K)
{
    __shared__ __align__(16) float As[16][64];   // [k][m]
    __shared__ __align__(16) float Bs[16][64];   // [k][n]
    const int bz = blockIdx.z;
    const float* xb = Bmat + (size_t)bz * K * HWF;
    const int m0 = blockIdx.y * 64, n0 = blockIdx.x * 64;
    const int tid = threadIdx.x;
    const int tx = tid & 15, ty = tid >> 4;
    const int ar = tid >> 2, ak = (tid & 3) * 4;
    const int br = tid >> 4, bc = (tid & 15) * 4;
    float acc[4][4] = {};
    for (int k0 = 0; k0 < K; k0 += 16) {
        float4 av = make_float4(0.f, 0.f, 0.f, 0.f);
        if (m0 + ar < M) av = *(const float4*)&w[(size_t)(m0 + ar) * K + k0 + ak];
        As[ak + 0][ar] = av.x; As[ak + 1][ar] = av.y;
        As[ak + 2][ar] = av.z; As[ak + 3][ar] = av.w;
        *(float4*)&Bs[br][bc] = *(const float4*)&xb[(size_t)(k0 + br) * HWF + n0 + bc];
        __syncthreads();
#pragma unroll
        for (int kk = 0; kk < 16; kk++) {
            float4 a4 = *(float4*)&As[kk][ty * 4];
            float4 b4 = *(float4*)&Bs[kk][tx * 4];
            float a[4]  = {a4.x, a4.y, a4.z, a4.w};
            float bq[4] = {b4.x, b4.y, b4.z, b4.w};
#pragma unroll
            for (int i = 0; i < 4; i++)
#pragma unroll
                for (int j = 0; j < 4; j++)
                    acc[i][j] = fmaf(a[i], bq[j], acc[i][j]);
        }
        __syncthreads();
    }
#pragma unroll
    for (int i = 0; i < 4; i++) {
        int o = m0 + ty * 4 + i;
        if (o >= M) break;
        float alpha = ss[o] * rsqrtf(vv[o] + EPSV);
        float beta  = fmaf(bb[o] - mm[o], alpha, tt[o]);
#pragma unroll
        for (int j = 0; j < 4; j++) {
            float v2 = fmaf(acc[i][j], alpha, beta);
            y[((size_t)bz * M + o) * HWF + n0 + tx * 4 + j] = fmaxf(v2, 0.f);
        }
    }
}

// =====================================================================
// 2x2 max pool: out[b][c][h2*32+w2]
// =====================================================================
__global__ void pool_kernel(const float* __restrict__ y, float* __restrict__ out, int Ch)
{
    int idx = blockIdx.x * blockDim.x + threadIdx.x;
    int total = NB * Ch * HW4;
    if (idx >= total) return;
    int n = idx & 1023;
    int c = (idx >> 10) % Ch;
    int bz = idx / (Ch * 1024);
    int h2 = n >> 5, w2 = n & 31;
    const float* p = y + ((size_t)bz * Ch + c) * HWF + (h2 * 2) * 64 + w2 * 2;
    out[idx] = fmaxf(fmaxf(p[0], p[1]), fmaxf(p[64], p[65]));
}

// =====================================================================
// scores: st[b][m][n] = sum_{k<32} g[b][k][m] * f[b][k][n]
// grid (16 n-tiles, 64 m-tiles, 8). Single K step (K=32).
// =====================================================================
__global__ void st_kernel()
{
    __shared__ __align__(16) float Gs[32][64];   // [k][m]
    __shared__ __align__(16) float Fs[32][64];   // [k][n]
    const int bz = blockIdx.z;
    const int m0 = blockIdx.y * 64, n0 = blockIdx.x * 64;
    const int tid = threadIdx.x;
    const int tx = tid & 15, ty = tid >> 4;
    const int lr = tid >> 3, lc = (tid & 7) * 8;
    const float* gp = g_gm + ((size_t)bz * 32 + lr) * HWF + m0 + lc;
    const float* fp = g_f  + ((size_t)bz * 32 + lr) * HW4 + n0 + lc;
    *(float4*)&Gs[lr][lc]     = *(const float4*)gp;
    *(float4*)&Gs[lr][lc + 4] = *(const float4*)(gp + 4);
    *(float4*)&Fs[lr][lc]     = *(const float4*)fp;
    *(float4*)&Fs[lr][lc + 4] = *(const float4*)(fp + 4);
    __syncthreads();
    float acc[4][4] = {};
#pragma unroll
    for (int kk = 0; kk < 32; kk++) {
        float4 a4 = *(float4*)&Gs[kk][ty * 4];
        float4 b4 = *(float4*)&Fs[kk][tx * 4];
        float a[4]  = {a4.x, a4.y, a4.z, a4.w};
        float bq[4] = {b4.x, b4.y, b4.z, b4.w};
#pragma unroll
        for (int i = 0; i < 4; i++)
#pragma unroll
            for (int j = 0; j < 4; j++)
                acc[i][j] = fmaf(a[i], bq[j], acc[i][j]);
    }
#pragma unroll
    for (int i = 0; i < 4; i++)
#pragma unroll
        for (int j = 0; j < 4; j++)
            g_st[((size_t)bz * HWF + m0 + ty * 4 + i) * HW4 + n0 + tx * 4 + j] = acc[i][j];
}

// =====================================================================
// softmax over n (1024 contiguous) per (b,m) row, in-place
// =====================================================================
__global__ void softmax_kernel()
{
    __shared__ float red[256];
    float* p = g_st + (size_t)blockIdx.x * HW4;
    const int tid = threadIdx.x;
    float4 v = *(float4*)&p[tid * 4];
    float mx = fmaxf(fmaxf(v.x, v.y), fmaxf(v.z, v.w));
    red[tid] = mx; __syncthreads();
    for (int s2 = 128; s2 > 0; s2 >>= 1) {
        if (tid < s2) red[tid] = fmaxf(red[tid], red[tid + s2]);
        __syncthreads();
    }
    mx = red[0];
    __syncthreads();
    v.x = expf(v.x - mx); v.y = expf(v.y - mx);
    v.z = expf(v.z - mx); v.w = expf(v.w - mx);
    red[tid] = v.x + v.y + v.z + v.w; __syncthreads();
    for (int s2 = 128; s2 > 0; s2 >>= 1) {
        if (tid < s2) red[tid] += red[tid + s2];
        __syncthreads();
    }
    float inv = 1.f / red[0];
    v.x *= inv; v.y *= inv; v.z *= inv; v.w *= inv;
    *(float4*)&p[tid * 4] = v;
}

// =====================================================================
// o[b][c][m] = sum_n hh[b][c][n] * st[b][m][n]   (NT GEMM, K=1024)
// BM=128 (all c), BN=64, BK=16; 256 threads, 8x4 per thread. grid (64,1,8)
// =====================================================================
__global__ void o_kernel()
{
    __shared__ __align__(16) float As[16][128];  // [k][c]
    __shared__ __align__(16) float Bs[16][64];   // [k][m]
    const int bz = blockIdx.z;
    const int m0 = blockIdx.x * 64;
    const int tid = threadIdx.x;
    const int tx = tid & 15, ty = tid >> 4;
    const int ar = tid >> 1, ak = (tid & 1) * 8;
    const int br = tid >> 2, bk = (tid & 3) * 4;
    const float* ap = g_hh + ((size_t)bz * 128 + ar) * HW4;
    const float* bp = g_st + ((size_t)bz * HWF + m0 + br) * HW4;
    float acc[8][4] = {};
    for (int k0 = 0; k0 < HW4; k0 += 16) {
        float4 a0 = *(const float4*)&ap[k0 + ak];
        float4 a1 = *(const float4*)&ap[k0 + ak + 4];
        As[ak + 0][ar] = a0.x; As[ak + 1][ar] = a0.y;
        As[ak + 2][ar] = a0.z; As[ak + 3][ar] = a0.w;
        As[ak + 4][ar] = a1.x; As[ak + 5][ar] = a1.y;
        As[ak + 6][ar] = a1.z; As[ak + 7][ar] = a1.w;
        float4 bv = *(const float4*)&bp[k0 + bk];
        Bs[bk + 0][br] = bv.x; Bs[bk + 1][br] = bv.y;
        Bs[bk + 2][br] = bv.z; Bs[bk + 3][br] = bv.w;
        __syncthreads();
#pragma unroll
        for (int kk = 0; kk < 16; kk++) {
            float4 b4  = *(float4*)&Bs[kk][tx * 4];
            float4 a0r = *(float4*)&As[kk][ty * 8];
            float4 a1r = *(float4*)&As[kk][ty * 8 + 4];
            float a[8]  = {a0r.x, a0r.y, a0r.z, a0r.w, a1r.x, a1r.y, a1r.z, a1r.w};
            float bq[4] = {b4.x, b4.y, b4.z, b4.w};
#pragma unroll
            for (int i = 0; i < 8; i++)
#pragma unroll
                for (int j = 0; j < 4; j++)
                    acc[i][j] = fmaf(a[i], bq[j], acc[i][j]);
        }
        __syncthreads();
    }
#pragma unroll
    for (int i = 0; i < 8; i++) {
        int c = ty * 8 + i;
#pragma unroll
        for (int j = 0; j < 4; j++)
            g_o[((size_t)bz * 128 + c) * HWF + m0 + tx * 4 + j] = acc[i][j];
    }
}

// =====================================================================
// final: out[b][o][p] = gamma * ( conv4(o)[o,p]*alpha + beta ) + x[b][o][p]
// M=256, K=128. grid (64, 4, 8)
// =====================================================================
__global__ void final_kernel(const float* __restrict__ w,
                             const float* __restrict__ bb, const float* __restrict__ ss,
                             const float* __restrict__ tt, const float* __restrict__ mm,
                             const float* __restrict__ vv,
                             const float* __restrict__ x, const float* __restrict__ gamma,
                             float* __restrict__ out)
{
    __shared__ __align__(16) float As[16][64];
    __shared__ __align__(16) float Bs[16][64];
    const int K = 128, M = 256;
    const int bz = blockIdx.z;
    const float* xb = g_o + (size_t)bz * K * HWF;
    const int m0 = blockIdx.y * 64, n0 = blockIdx.x * 64;
    const int tid = threadIdx.x;
    const int tx = tid & 15, ty = tid >> 4;
    const int ar = tid >> 2, ak = (tid & 3) * 4;
    const int br = tid >> 4, bc = (tid & 15) * 4;
    float acc[4][4] = {};
    for (int k0 = 0; k0 < K; k0 += 16) {
        float4 av = *(const float4*)&w[(size_t)(m0 + ar) * K + k0 + ak];
        As[ak + 0][ar] = av.x; As[ak + 1][ar] = av.y;
        As[ak + 2][ar] = av.z; As[ak + 3][ar] = av.w;
        *(float4*)&Bs[br][bc] = *(const float4*)&xb[(size_t)(k0 + br) * HWF + n0 + bc];
        __syncthreads();
#pragma unroll
        for (int kk = 0; kk < 16; kk++) {
            float4 a4 = *(float4*)&As[kk][ty * 4];
            float4 b4 = *(float4*)&Bs[kk][tx * 4];
            float a[4]  = {a4.x, a4.y, a4.z, a4.w};
            float bq[4] = {b4.x, b4.y, b4.z, b4.w};
#pragma unroll
            for (int i = 0; i < 4; i++)
#pragma unroll
                for (int j = 0; j < 4; j++)
                    acc[i][j] = fmaf(a[i], bq[j], acc[i][j]);
        }
        __syncthreads();
    }
    float gm = *gamma;
#pragma unroll
    for (int i = 0; i < 4; i++) {
        int o = m0 + ty * 4 + i;
        float alpha = ss[o] * rsqrtf(vv[o] + EPSV);
        float beta  = fmaf(bb[o] - mm[o], alpha, tt[o]);
#pragma unroll
        for (int j = 0; j < 4; j++) {
            float v2 = fmaf(acc[i][j], alpha, beta);
            size_t idx = ((size_t)bz * NC + o) * HWF + n0 + tx * 4 + j;
            out[idx] = fmaf(gm, v2, x[idx]);
        }
    }
}

// =====================================================================
extern "C" void kernel_launch(void* const* d_in, const int* in_sizes, int n_in,
                              void* d_out, int out_size)
{
    const float* x  = (const float*)d_in[0];
    const float* w1 = (const float*)d_in[1],  *b1 = (const float*)d_in[2],
               * s1 = (const float*)d_in[3],  *t1 = (const float*)d_in[4],
               * m1 = (const float*)d_in[5],  *v1 = (const float*)d_in[6];
    const float* w2 = (const float*)d_in[7],  *b2 = (const float*)d_in[8],
               * s2 = (const float*)d_in[9],  *t2 = (const float*)d_in[10],
               * m2 = (const float*)d_in[11], *v2 = (const float*)d_in[12];
    const float* w3 = (const float*)d_in[13], *b3 = (const float*)d_in[14],
               * s3 = (const float*)d_in[15], *t3 = (const float*)d_in[16],
               * m3 = (const float*)d_in[17], *v3 = (const float*)d_in[18];
    const float* w4 = (const float*)d_in[19], *b4 = (const float*)d_in[20],
               * s4 = (const float*)d_in[21], *t4 = (const float*)d_in[22],
               * m4 = (const float*)d_in[23], *v4 = (const float*)d_in[24];
    const float* gamma = (const float*)d_in[25];
    float* out = (float*)d_out;

    float *py1, *py3, *pf, *pgm, *phh;
    cudaGetSymbolAddress((void**)&py1, g_y1);
    cudaGetSymbolAddress((void**)&py3, g_y3);
    cudaGetSymbolAddress((void**)&pf,  g_f);
    cudaGetSymbolAddress((void**)&pgm, g_gm);
    cudaGetSymbolAddress((void**)&phh, g_hh);

    // projections (conv1x1 + BN + ReLU)
    proj_kernel<<<dim3(64, 1, NB), 256>>>(x, w1, b1, s1, t1, m1, v1, py1, 32,  NC);
    proj_kernel<<<dim3(64, 1, NB), 256>>>(x, w2, b2, s2, t2, m2, v2, pgm, 32,  NC);
    proj_kernel<<<dim3(64, 2, NB), 256>>>(x, w3, b3, s3, t3, m3, v3, py3, 128, NC);

    // 2x2 maxpool
    pool_kernel<<<(NB * 32  * HW4 + 255) / 256, 256>>>(py1, pf,  32);
    pool_kernel<<<(NB * 128 * HW4 + 255) / 256, 256>>>(py3, phh, 128);

    // scores st[b][m][n] = g^T f  (m-major so softmax axis is contiguous)
    st_kernel<<<dim3(16, 64, NB), 256>>>();

    // softmax over keys n per (b, m)
    softmax_kernel<<<NB * HWF, 256>>>();

    // o = hh · beta
    o_kernel<<<dim3(64, 1, NB), 256>>>();

    // conv4 + BN + gamma*out + x
    final_kernel<<<dim3(64, 4, NB), 256>>>(w4, b4, s4, t4, m4, v4, x, gamma, out);
}

// round 3
// speedup vs baseline: 3.1422x; 3.1422x over previous
#include <cuda_runtime.h>
#include <math.h>

#define NB 8
#define NC 256
#define HWF 4096
#define HW4 1024
#define EPSV 1e-5f

// ---------------- scratch (static __device__, no allocation) ----------------
__device__ float    g_wTp[256 * 192];                // stacked wT for proj: [k=256][m=192] (w1|w2|w3)
__device__ float    g_w4T[128 * 256];                // w4T: [k=128][m=256]
__device__ float    g_abp[2 * 192];                  // proj alpha/beta (BN folded)
__device__ float    g_ab4[2 * 256];                  // final alpha/beta
__device__ unsigned g_mxe[NB * HWF];                 // encoded col-max of scores per (b,m)
__device__ float    g_y1[NB * 32  * HWF];            // conv1 pre-pool [b][c][p]
__device__ float    g_y3[NB * 128 * HWF];            // conv3 pre-pool [b][c][p]
__device__ float    g_f [NB * 32  * HW4];            // pooled f  [b][k][n]
__device__ float    g_gm[NB * 32  * HWF];            // g         [b][k][m]
__device__ float    g_hh[NB * HW4 * 128];            // pooled hh TRANSPOSED [b][n][c]
__device__ float    g_st[(size_t)NB * HW4 * HWF];    // scores st[b][n][m]  (134 MB)
__device__ float    g_o [NB * 128 * HWF];            // attention out [b][c][m]

// ---------------- helpers ----------------
__device__ __forceinline__ unsigned tf32r(float f) {
    unsigned r; asm("cvt.rna.tf32.f32 %0, %1;" : "=r"(r) : "f"(f)); return r;
}
__device__ __forceinline__ unsigned fenc(float f) {   // monotone float->uint
    unsigned u = __float_as_uint(f);
    return (u & 0x80000000u) ? ~u : (u | 0x80000000u);
}
__device__ __forceinline__ float fdec(unsigned u) {
    return (u & 0x80000000u) ? __uint_as_float(u ^ 0x80000000u) : __uint_as_float(~u);
}
__device__ __forceinline__ void mma8(float* d, const unsigned* a, const unsigned* b) {
    asm volatile(
        "mma.sync.aligned.m16n8k8.row.col.f32.tf32.tf32.f32 "
        "{%0,%1,%2,%3},{%4,%5,%6,%7},{%8,%9},{%0,%1,%2,%3};"
        : "+f"(d[0]), "+f"(d[1]), "+f"(d[2]), "+f"(d[3])
        : "r"(a[0]), "r"(a[1]), "r"(a[2]), "r"(a[3]), "r"(b[0]), "r"(b[1]));
}

// one 32-deep k-tile of mma on staged smem (As[k][m] stride AS, Bs[k][n] stride BS)
template<int MF, int NF, int AS, int BS>
__device__ __forceinline__ void mma_ktile(const unsigned* As, const unsigned* Bs,
                                          int mBase, int nBase, int g, int tig,
                                          float (*acc)[NF][4])
{
#pragma unroll
    for (int ks = 0; ks < 4; ks++) {
        unsigned a[MF][4], b[NF][2];
        const unsigned* Ap = As + (ks * 8 + tig) * AS;
        const unsigned* Bp = Bs + (ks * 8 + tig) * BS;
#pragma unroll
        for (int i = 0; i < MF; i++) {
            const unsigned* p = Ap + mBase + i * 16 + g;
            a[i][0] = p[0]; a[i][1] = p[8];
            a[i][2] = p[4 * AS]; a[i][3] = p[4 * AS + 8];
        }
#pragma unroll
        for (int j = 0; j < NF; j++) {
            const unsigned* p = Bp + nBase + j * 8 + g;
            b[j][0] = p[0]; b[j][1] = p[4 * BS];
        }
#pragma unroll
        for (int i = 0; i < MF; i++)
#pragma unroll
            for (int j = 0; j < NF; j++)
                mma8(acc[i][j], a[i], b[j]);
    }
}

// =====================================================================
// pre: build transposed weights, folded BN params, init colmax
// =====================================================================
__global__ void pre_kernel(const float* __restrict__ w1, const float* __restrict__ w2,
                           const float* __restrict__ w3, const float* __restrict__ w4,
                           const float* __restrict__ b1, const float* __restrict__ s1,
                           const float* __restrict__ t1, const float* __restrict__ m1,
                           const float* __restrict__ v1,
                           const float* __restrict__ b2, const float* __restrict__ s2,
                           const float* __restrict__ t2, const float* __restrict__ m2,
                           const float* __restrict__ v2,
                           const float* __restrict__ b3, const float* __restrict__ s3,
                           const float* __restrict__ t3, const float* __restrict__ m3,
                           const float* __restrict__ v3,
                           const float* __restrict__ b4, const float* __restrict__ s4,
                           const float* __restrict__ t4, const float* __restrict__ m4,
                           const float* __restrict__ v4)
{
    int idx = blockIdx.x * 256 + threadIdx.x;
    if (idx < 49152) {                       // wTp [k][m], m: 0-31 w1, 32-63 w2, 64-191 w3
        int k = idx / 192, m = idx % 192;
        float val = (m < 32) ? w1[m * 256 + k]
                  : (m < 64) ? w2[(m - 32) * 256 + k]
                             : w3[(m - 64) * 256 + k];
        g_wTp[idx] = val;
        return;
    }
    idx -= 49152;
    if (idx < 32768) {                       // w4T [k][m]
        int k = idx / 256, m = idx % 256;
        g_w4T[idx] = w4[m * 128 + k];
        return;
    }
    idx -= 32768;
    if (idx < 192) {                         // proj BN fold
        int r = idx;
        float bb, ss, tt, mm, vv;
        if (r < 32)      { bb = b1[r];      ss = s1[r];      tt = t1[r];      mm = m1[r];      vv = v1[r]; }
        else if (r < 64) { bb = b2[r - 32]; ss = s2[r - 32]; tt = t2[r - 32]; mm = m2[r - 32]; vv = v2[r - 32]; }
        else             { bb = b3[r - 64]; ss = s3[r - 64]; tt = t3[r - 64]; mm = m3[r - 64]; vv = v3[r - 64]; }
        float alpha = ss * rsqrtf(vv + EPSV);
        g_abp[r]       = alpha;
        g_abp[192 + r] = fmaf(bb - mm, alpha, tt);
        return;
    }
    idx -= 192;
    if (idx < 256) {                         // final BN fold
        int r = idx;
        float alpha = s4[r] * rsqrtf(v4[r] + EPSV);
        g_ab4[r]       = alpha;
        g_ab4[256 + r] = fmaf(b4[r] - m4[r], alpha, t4[r]);
        return;
    }
    idx -= 256;
    if (idx < NB * HWF) g_mxe[idx] = 0u;     // encoded -inf
}

// =====================================================================
// proj: all three conv1x1+BN+ReLU as one GEMM. M=192, K=256, N=4096 per b.
// BM=64, BN=128, 8 warps (2x4), MF=2, NF=4. grid (32, 3, NB)
// =====================================================================
__global__ __launch_bounds__(256) void proj_mma_kernel(const float* __restrict__ x)
{
    __shared__ unsigned As[32 * 72];
    __shared__ unsigned Bs[32 * 136];
    const int b = blockIdx.z;
    const int m0 = blockIdx.y * 64, p0 = blockIdx.x * 128;
    const int t = threadIdx.x, lane = t & 31, w = t >> 5;
    const int g = lane >> 2, tig = lane & 3;
    const int mBase = (w >> 2) * 32, nBase = (w & 3) * 32;
    const float* xb = x + ((size_t)b << 20);
    float acc[2][4][4] = {};
    for (int kt = 0; kt < 8; kt++) {
        const int k0 = kt * 32;
        // A: wTp[k0:32][m0:64]
#pragma unroll
        for (int p = 0; p < 2; p++) {
            int slot = t + p * 256, r = slot >> 4, c4 = (slot & 15) * 4;
            float4 v = *(const float4*)&g_wTp[(k0 + r) * 192 + m0 + c4];
            unsigned* d = &As[r * 72 + c4];
            d[0] = tf32r(v.x); d[1] = tf32r(v.y); d[2] = tf32r(v.z); d[3] = tf32r(v.w);
        }
        // B: x[k0:32][p0:128]
#pragma unroll
        for (int p = 0; p < 4; p++) {
            int slot = t + p * 256, r = slot >> 5, c4 = (slot & 31) * 4;
            float4 v = *(const float4*)&xb[((size_t)(k0 + r) << 12) + p0 + c4];
            unsigned* d = &Bs[r * 136 + c4];
            d[0] = tf32r(v.x); d[1] = tf32r(v.y); d[2] = tf32r(v.z); d[3] = tf32r(v.w);
        }
        __syncthreads();
        mma_ktile<2, 4, 72, 136>(As, Bs, mBase, nBase, g, tig, acc);
        __syncthreads();
    }
    // epilogue: BN + ReLU, route to y1 / g / y3
#pragma unroll
    for (int i = 0; i < 2; i++) {
#pragma unroll
        for (int half = 0; half < 2; half++) {
            int r = m0 + mBase + i * 16 + g + half * 8;
            float alpha = g_abp[r], beta = g_abp[192 + r];
            float* dst;
            if (r < 32)      dst = g_y1 + ((size_t)(b * 32 + r) << 12);
            else if (r < 64) dst = g_gm + ((size_t)(b * 32 + (r - 32)) << 12);
            else             dst = g_y3 + ((size_t)(b * 128 + (r - 64)) << 12);
#pragma unroll
            for (int j = 0; j < 4; j++) {
                int col = p0 + nBase + j * 8 + 2 * tig;
                float2 o;
                o.x = fmaxf(fmaf(acc[i][j][half * 2 + 0], alpha, beta), 0.f);
                o.y = fmaxf(fmaf(acc[i][j][half * 2 + 1], alpha, beta), 0.f);
                *(float2*)&dst[col] = o;
            }
        }
    }
}

// =====================================================================
// pool f: y1 -> g_f[b][k][n]
// =====================================================================
__global__ void pool_f_kernel()
{
    int idx = blockIdx.x * 256 + threadIdx.x;
    if (idx >= NB * 32 * HW4) return;
    int n = idx & 1023, c = (idx >> 10) & 31, b = idx >> 15;
    int h2 = n >> 5, w2 = n & 31;
    const float* p = g_y1 + ((size_t)(b * 32 + c) << 12) + h2 * 128 + w2 * 2;
    g_f[idx] = fmaxf(fmaxf(p[0], p[1]), fmaxf(p[64], p[65]));
}

// =====================================================================
// pool hh (transposed): y3[b][c][sp] -> g_hh[b][n][c]. grid (32, 4, NB), 256 thr
// =====================================================================
__global__ void pool_hh_kernel()
{
    __shared__ float tile[32][33];
    const int b = blockIdx.z, c0 = blockIdx.y * 32, n0 = blockIdx.x * 32;
    const int t = threadIdx.x, tx = t & 31, ty = t >> 5;   // tx = n, ty = c group (8)
    const float* y3b = g_y3 + ((size_t)b * 128 << 12);
    const int n = n0 + tx, h2 = n >> 5, w2 = n & 31;
#pragma unroll
    for (int it = 0; it < 4; it++) {
        int c = ty + it * 8;
        const float* p = y3b + ((size_t)(c0 + c) << 12) + h2 * 128 + w2 * 2;
        tile[tx][c] = fmaxf(fmaxf(p[0], p[1]), fmaxf(p[64], p[65]));
    }
    __syncthreads();
    const int nl = t >> 3, c4 = (t & 7) * 4;
    float4 v = make_float4(tile[nl][c4], tile[nl][c4 + 1], tile[nl][c4 + 2], tile[nl][c4 + 3]);
    *(float4*)&g_hh[(size_t)(b * 1024 + n0 + nl) * 128 + c0 + c4] = v;
}

// =====================================================================
// scores: st[b][n][m] = sum_k f[k][n] g[k][m], K=32. Col-max -> g_mxe (atomic).
// BM(n)=128, BN(m)=128, MF=4, NF=4. grid (32, 8, NB)
// =====================================================================
__global__ __launch_bounds__(256) void st_mma_kernel()
{
    __shared__ unsigned As[32 * 136];
    __shared__ unsigned Bs[32 * 136];
    __shared__ unsigned cm[128];
    const int b = blockIdx.z;
    const int n0 = blockIdx.y * 128, m0 = blockIdx.x * 128;
    const int t = threadIdx.x, lane = t & 31, w = t >> 5;
    const int g = lane >> 2, tig = lane & 3;
    const int mBase = (w >> 2) * 64, nBase = (w & 3) * 32;
    if (t < 128) cm[t] = 0u;
    const float* fb = g_f  + (size_t)b * 32 * 1024;
    const float* gb = g_gm + (size_t)b * 32 * 4096;
    float acc[4][4][4] = {};
#pragma unroll
    for (int p = 0; p < 4; p++) {
        int slot = t + p * 256, r = slot >> 5, c4 = (slot & 31) * 4;
        float4 v = *(const float4*)&fb[r * 1024 + n0 + c4];
        unsigned* d = &As[r * 136 + c4];
        d[0] = tf32r(v.x); d[1] = tf32r(v.y); d[2] = tf32r(v.z); d[3] = tf32r(v.w);
        float4 u = *(const float4*)&gb[(size_t)r * 4096 + m0 + c4];
        unsigned* e = &Bs[r * 136 + c4];
        e[0] = tf32r(u.x); e[1] = tf32r(u.y); e[2] = tf32r(u.z); e[3] = tf32r(u.w);
    }
    __syncthreads();
    mma_ktile<4, 4, 136, 136>(As, Bs, mBase, nBase, g, tig, acc);
    // write scores + collect col-max
    float* stb = g_st + ((size_t)b << 22);
#pragma unroll
    for (int j = 0; j < 4; j++) {
        int col = nBase + j * 8 + 2 * tig;
        float mx0 = -1e30f, mx1 = -1e30f;
#pragma unroll
        for (int i = 0; i < 4; i++) {
            int row = n0 + mBase + i * 16 + g;
            *(float2*)&stb[(size_t)row * 4096 + m0 + col]       = make_float2(acc[i][j][0], acc[i][j][1]);
            *(float2*)&stb[(size_t)(row + 8) * 4096 + m0 + col] = make_float2(acc[i][j][2], acc[i][j][3]);
            mx0 = fmaxf(mx0, fmaxf(acc[i][j][0], acc[i][j][2]));
            mx1 = fmaxf(mx1, fmaxf(acc[i][j][1], acc[i][j][3]));
        }
        atomicMax(&cm[col],     fenc(mx0));
        atomicMax(&cm[col + 1], fenc(mx1));
    }
    __syncthreads();
    if (t < 128) atomicMax(&g_mxe[b * 4096 + m0 + t], cm[t]);
}

// =====================================================================
// o[b][c][m] = softmax-weighted sum: GEMM M=c(128), N=m(128/blk), K=n(1024)
// B staging applies exp(st - mx[m]); col-sums accumulated; epilogue scales 1/sum.
// MF=4, NF=4. grid (32, NB)
// =====================================================================
__global__ __launch_bounds__(256) void o_mma_kernel()
{
    __shared__ unsigned As[32 * 136];
    __shared__ unsigned Bs[32 * 136];
    __shared__ float colsum[128];
    const int b = blockIdx.y, m0 = blockIdx.x * 128;
    const int t = threadIdx.x, lane = t & 31, w = t >> 5;
    const int g = lane >> 2, tig = lane & 3;
    const int mBase = (w >> 2) * 64, nBase = (w & 3) * 32;
    const int m4 = (t & 31) * 4, krow = t >> 5;
    if (t < 128) colsum[t] = 0.f;
    float mxv[4];
#pragma unroll
    for (int j = 0; j < 4; j++) mxv[j] = fdec(g_mxe[b * 4096 + m0 + m4 + j]);
    float esum[4] = {0.f, 0.f, 0.f, 0.f};
    const float* hhb = g_hh + (size_t)b * 1024 * 128;
    const float* stb = g_st + ((size_t)b << 22);
    float acc[4][4][4] = {};
    for (int kt = 0; kt < 32; kt++) {
        const int k0 = kt * 32;
        // A: hh[k0:32][0:128]  (contiguous)
#pragma unroll
        for (int p = 0; p < 4; p++) {
            int slot = t + p * 256, r = slot >> 5, c4 = (slot & 31) * 4;
            float4 v = *(const float4*)&hhb[(k0 + r) * 128 + c4];
            unsigned* d = &As[r * 136 + c4];
            d[0] = tf32r(v.x); d[1] = tf32r(v.y); d[2] = tf32r(v.z); d[3] = tf32r(v.w);
        }
        // B: exp(st[k0:32][m0:128] - mx)
#pragma unroll
        for (int p = 0; p < 4; p++) {
            int r = krow + p * 8;
            float4 v = *(const float4*)&stb[(size_t)(k0 + r) * 4096 + m0 + m4];
            float e0 = __expf(v.x - mxv[0]), e1 = __expf(v.y - mxv[1]);
            float e2 = __expf(v.z - mxv[2]), e3 = __expf(v.w - mxv[3]);
            esum[0] += e0; esum[1] += e1; esum[2] += e2; esum[3] += e3;
            unsigned* d = &Bs[r * 136 + m4];
            d[0] = tf32r(e0); d[1] = tf32r(e1); d[2] = tf32r(e2); d[3] = tf32r(e3);
        }
        __syncthreads();
        mma_ktile<4, 4, 136, 136>(As, Bs, mBase, nBase, g, tig, acc);
        __syncthreads();
    }
#pragma unroll
    for (int j = 0; j < 4; j++) atomicAdd(&colsum[m4 + j], esum[j]);
    __syncthreads();
    float* ob = g_o + (size_t)b * 128 * 4096;
#pragma unroll
    for (int j = 0; j < 4; j++) {
        int col = nBase + j * 8 + 2 * tig;
        float inv0 = 1.f / colsum[col], inv1 = 1.f / colsum[col + 1];
#pragma unroll
        for (int i = 0; i < 4; i++) {
            int row = mBase + i * 16 + g;
            *(float2*)&ob[(size_t)row * 4096 + m0 + col] =
                make_float2(acc[i][j][0] * inv0, acc[i][j][1] * inv1);
            *(float2*)&ob[(size_t)(row + 8) * 4096 + m0 + col] =
                make_float2(acc[i][j][2] * inv0, acc[i][j][3] * inv1);
        }
    }
}

// =====================================================================
// final: out = gamma*(BN(conv4(o))) + x. M=256, K=128, N=4096 per b.
// BM=128, BN=128, MF=4, NF=4. grid (32, 2, NB)
// =====================================================================
__global__ __launch_bounds__(256) void final_mma_kernel(const float* __restrict__ x,
                                                        const float* __restrict__ gamma,
                                                        float* __restrict__ out)
{
    __shared__ unsigned As[32 * 136];
    __shared__ unsigned Bs[32 * 136];
    const int b = blockIdx.z;
    const int m0 = blockIdx.y * 128, p0 = blockIdx.x * 128;
    const int t = threadIdx.x, lane = t & 31, w = t >> 5;
    const int g = lane >> 2, tig = lane & 3;
    const int mBase = (w >> 2) * 64, nBase = (w & 3) * 32;
    const float* ob = g_o + (size_t)b * 128 * 4096;
    float acc[4][4][4] = {};
    for (int kt = 0; kt < 4; kt++) {
        const int k0 = kt * 32;
#pragma unroll
        for (int p = 0; p < 4; p++) {
            int slot = t + p * 256, r = slot >> 5, c4 = (slot & 31) * 4;
            float4 v = *(const float4*)&g_w4T[(k0 + r) * 256 + m0 + c4];
            unsigned* d = &As[r * 136 + c4];
            d[0] = tf32r(v.x); d[1] = tf32r(v.y); d[2] = tf32r(v.z); d[3] = tf32r(v.w);
            float4 u = *(const float4*)&ob[(size_t)(k0 + r) * 4096 + p0 + c4];
            unsigned* e = &Bs[r * 136 + c4];
            e[0] = tf32r(u.x); e[1] = tf32r(u.y); e[2] = tf32r(u.z); e[3] = tf32r(u.w);
        }
        __syncthreads();
        mma_ktile<4, 4, 136, 136>(As, Bs, mBase, nBase, g, tig, acc);
        __syncthreads();
    }
    const float gm = *gamma;
#pragma unroll
    for (int i = 0; i < 4; i++) {
#pragma unroll
        for (int half = 0; half < 2; half++) {
            int r = m0 + mBase + i * 16 + g + half * 8;
            float alpha = g_ab4[r], beta = g_ab4[256 + r];
            size_t base = ((size_t)(b * 256 + r) << 12) + p0;
#pragma unroll
            for (int j = 0; j < 4; j++) {
                int col = nBase + j * 8 + 2 * tig;
                float2 xv = *(const float2*)&x[base + col];
                float2 o;
                o.x = fmaf(gm, fmaf(acc[i][j][half * 2 + 0], alpha, beta), xv.x);
                o.y = fmaf(gm, fmaf(acc[i][j][half * 2 + 1], alpha, beta), xv.y);
                *(float2*)&out[base + col] = o;
            }
        }
    }
}

// =====================================================================
extern "C" void kernel_launch(void* const* d_in, const int* in_sizes, int n_in,
                              void* d_out, int out_size)
{
    const float* x  = (const float*)d_in[0];
    const float* w1 = (const float*)d_in[1],  *b1 = (const float*)d_in[2],
               * s1 = (const float*)d_in[3],  *t1 = (const float*)d_in[4],
               * m1 = (const float*)d_in[5],  *v1 = (const float*)d_in[6];
    const float* w2 = (const float*)d_in[7],  *b2 = (const float*)d_in[8],
               * s2 = (const float*)d_in[9],  *t2 = (const float*)d_in[10],
               * m2 = (const float*)d_in[11], *v2 = (const float*)d_in[12];
    const float* w3 = (const float*)d_in[13], *b3 = (const float*)d_in[14],
               * s3 = (const float*)d_in[15], *t3 = (const float*)d_in[16],
               * m3 = (const float*)d_in[17], *v3 = (const float*)d_in[18];
    const float* w4 = (const float*)d_in[19], *b4 = (const float*)d_in[20],
               * s4 = (const float*)d_in[21], *t4 = (const float*)d_in[22],
               * m4 = (const float*)d_in[23], *v4 = (const float*)d_in[24];
    const float* gamma = (const float*)d_in[25];
    float* out = (float*)d_out;

    pre_kernel<<<450, 256>>>(w1, w2, w3, w4,
                             b1, s1, t1, m1, v1,
                             b2, s2, t2, m2, v2,
                             b3, s3, t3, m3, v3,
                             b4, s4, t4, m4, v4);

    proj_mma_kernel<<<dim3(32, 3, NB), 256>>>(x);

    pool_f_kernel<<<(NB * 32 * HW4 + 255) / 256, 256>>>();
    pool_hh_kernel<<<dim3(32, 4, NB), 256>>>();

    st_mma_kernel<<<dim3(32, 8, NB), 256>>>();

    o_mma_kernel<<<dim3(32, NB), 256>>>();

    final_mma_kernel<<<dim3(32, 2, NB), 256>>>(x, gamma, out);
}

// round 4
// speedup vs baseline: 3.5740x; 1.1374x over previous
#include <cuda_runtime.h>
#include <math.h>

#define NB 8
#define NC 256
#define HWF 4096
#define HW4 1024
#define EPSV 1e-5f
#define LOG2E 1.4426950408889634f

// ---------------- scratch (static __device__, no allocation) ----------------
__device__ float g_wTp[256 * 192];             // stacked wT for proj [k=256][m=192], alpha-folded
__device__ float g_w4T[128 * 256];             // w4T [k=128][m=256], (gamma*alpha4)-folded
__device__ float g_abp[2 * 192];               // proj beta (alpha slot unused)
__device__ float g_ab4[2 * 256];               // final gamma*beta4 in [256..]
__device__ float g_f [NB * 32  * HW4];         // pooled f  [b][k][n]  (log2e folded)
__device__ float g_gm[NB * 32  * HWF];         // g         [b][k][m]
__device__ float g_hh[NB * HW4 * 128];         // pooled hh TRANSPOSED [b][n][c]
__device__ float g_o [NB * 128 * HWF];         // attention out [b][c][m]

// ---------------- helpers ----------------
__device__ __forceinline__ unsigned tf32r(float f) {
    unsigned r; asm("cvt.rna.tf32.f32 %0, %1;" : "=r"(r) : "f"(f)); return r;
}
__device__ __forceinline__ float ex2f(float f) {
    float r; asm("ex2.approx.ftz.f32 %0, %1;" : "=f"(r) : "f"(f)); return r;
}
__device__ __forceinline__ void mma8(float* d, const unsigned* a, const unsigned* b) {
    asm volatile(
        "mma.sync.aligned.m16n8k8.row.col.f32.tf32.tf32.f32 "
        "{%0,%1,%2,%3},{%4,%5,%6,%7},{%8,%9},{%0,%1,%2,%3};"
        : "+f"(d[0]), "+f"(d[1]), "+f"(d[2]), "+f"(d[3])
        : "r"(a[0]), "r"(a[1]), "r"(a[2]), "r"(a[3]), "r"(b[0]), "r"(b[1]));
}

// one 32-deep k-tile of mma on staged smem (As[k][m] stride AS, Bs[k][n] stride BS)
template<int MF, int NF, int AS, int BS>
__device__ __forceinline__ void mma_ktile(const unsigned* As, const unsigned* Bs,
                                          int mBase, int nBase, int g, int tig,
                                          float (*acc)[NF][4])
{
#pragma unroll
    for (int ks = 0; ks < 4; ks++) {
        unsigned a[MF][4], b[NF][2];
        const unsigned* Ap = As + (ks * 8 + tig) * AS;
        const unsigned* Bp = Bs + (ks * 8 + tig) * BS;
#pragma unroll
        for (int i = 0; i < MF; i++) {
            const unsigned* p = Ap + mBase + i * 16 + g;
            a[i][0] = p[0]; a[i][1] = p[8];
            a[i][2] = p[4 * AS]; a[i][3] = p[4 * AS + 8];
        }
#pragma unroll
        for (int j = 0; j < NF; j++) {
            const unsigned* p = Bp + nBase + j * 8 + g;
            b[j][0] = p[0]; b[j][1] = p[4 * BS];
        }
#pragma unroll
        for (int i = 0; i < MF; i++)
#pragma unroll
            for (int j = 0; j < NF; j++)
                mma8(acc[i][j], a[i], b[j]);
    }
}

// =====================================================================
// pre: transposed weights with BN alpha folded; beta vectors
// =====================================================================
__global__ void pre_kernel(const float* __restrict__ w1, const float* __restrict__ w2,
                           const float* __restrict__ w3, const float* __restrict__ w4,
                           const float* __restrict__ b1, const float* __restrict__ s1,
                           const float* __restrict__ t1, const float* __restrict__ m1,
                           const float* __restrict__ v1,
                           const float* __restrict__ b2, const float* __restrict__ s2,
                           const float* __restrict__ t2, const float* __restrict__ m2,
                           const float* __restrict__ v2,
                           const float* __restrict__ b3, const float* __restrict__ s3,
                           const float* __restrict__ t3, const float* __restrict__ m3,
                           const float* __restrict__ v3,
                           const float* __restrict__ b4, const float* __restrict__ s4,
                           const float* __restrict__ t4, const float* __restrict__ m4,
                           const float* __restrict__ v4,
                           const float* __restrict__ gamma)
{
    int idx = blockIdx.x * 256 + threadIdx.x;
    if (idx < 49152) {                       // wTp [k][m] with alpha (and log2e for f) folded
        int k = idx / 192, m = idx % 192;
        float val, alpha;
        if (m < 32)      { val = w1[m * 256 + k];        alpha = s1[m] * rsqrtf(v1[m] + EPSV) * LOG2E; }
        else if (m < 64) { val = w2[(m - 32) * 256 + k]; alpha = s2[m - 32] * rsqrtf(v2[m - 32] + EPSV); }
        else             { val = w3[(m - 64) * 256 + k]; alpha = s3[m - 64] * rsqrtf(v3[m - 64] + EPSV); }
        g_wTp[idx] = val * alpha;
        return;
    }
    idx -= 49152;
    if (idx < 32768) {                       // w4T [k][m] with gamma*alpha4 folded
        int k = idx / 256, m = idx % 256;
        float alpha = s4[m] * rsqrtf(v4[m] + EPSV) * gamma[0];
        g_w4T[idx] = w4[m * 128 + k] * alpha;
        return;
    }
    idx -= 32768;
    if (idx < 192) {                         // proj beta (post-alpha)
        int r = idx;
        float bb, ss, tt, mm, vv, lg = 1.f;
        if (r < 32)      { bb = b1[r];      ss = s1[r];      tt = t1[r];      mm = m1[r];      vv = v1[r]; lg = LOG2E; }
        else if (r < 64) { bb = b2[r - 32]; ss = s2[r - 32]; tt = t2[r - 32]; mm = m2[r - 32]; vv = v2[r - 32]; }
        else             { bb = b3[r - 64]; ss = s3[r - 64]; tt = t3[r - 64]; mm = m3[r - 64]; vv = v3[r - 64]; }
        float alpha = ss * rsqrtf(vv + EPSV);
        g_abp[192 + r] = fmaf(bb - mm, alpha, tt) * lg;
        return;
    }
    idx -= 192;
    if (idx < 256) {                         // final gamma*beta4
        int r = idx;
        float alpha = s4[r] * rsqrtf(v4[r] + EPSV);
        g_ab4[256 + r] = fmaf(b4[r] - m4[r], alpha, t4[r]) * gamma[0];
    }
}

// =====================================================================
// proj+pool: GEMM(M=64 slice of 192, K=256, N=128 spatial) + BN + ReLU
// then in-smem 2x2 pool and routing to f (x log2e already folded), g, hh^T.
// grid (32 p-tiles, 3 m-slices, NB), 256 threads.
// =====================================================================
__global__ __launch_bounds__(256) void proj_pool_kernel(const float* __restrict__ x)
{
    __shared__ union {
        struct { unsigned As[32 * 72]; unsigned Bs[32 * 136]; } s;
        float T[64 * 132];
    } u;
    const int b = blockIdx.z;
    const int my = blockIdx.y, m0 = my * 64;
    const int bx = blockIdx.x, p0 = bx * 128;
    const int t = threadIdx.x, lane = t & 31, w = t >> 5;
    const int g = lane >> 2, tig = lane & 3;
    const int mBase = (w >> 2) * 32, nBase = (w & 3) * 32;
    const float* xb = x + ((size_t)b << 20);
    float acc[2][4][4] = {};
    for (int kt = 0; kt < 8; kt++) {
        const int k0 = kt * 32;
#pragma unroll
        for (int p = 0; p < 2; p++) {
            int slot = t + p * 256, r = slot >> 4, c4 = (slot & 15) * 4;
            float4 v = *(const float4*)&g_wTp[(k0 + r) * 192 + m0 + c4];
            unsigned* d = &u.s.As[r * 72 + c4];
            d[0] = tf32r(v.x); d[1] = tf32r(v.y); d[2] = tf32r(v.z); d[3] = tf32r(v.w);
        }
#pragma unroll
        for (int p = 0; p < 4; p++) {
            int slot = t + p * 256, r = slot >> 5, c4 = (slot & 31) * 4;
            float4 v = *(const float4*)&xb[((size_t)(k0 + r) << 12) + p0 + c4];
            unsigned* d = &u.s.Bs[r * 136 + c4];
            d[0] = tf32r(v.x); d[1] = tf32r(v.y); d[2] = tf32r(v.z); d[3] = tf32r(v.w);
        }
        __syncthreads();
        mma_ktile<2, 4, 72, 136>(u.s.As, u.s.Bs, mBase, nBase, g, tig, acc);
        __syncthreads();
    }
    // BN + ReLU into smem tile T[m 64][p 128] (stride 132)
#pragma unroll
    for (int i = 0; i < 2; i++) {
#pragma unroll
        for (int half = 0; half < 2; half++) {
            int rl = mBase + i * 16 + g + half * 8;
            float beta = g_abp[192 + m0 + rl];
#pragma unroll
            for (int j = 0; j < 4; j++) {
                int col = nBase + j * 8 + 2 * tig;
                u.T[rl * 132 + col]     = fmaxf(acc[i][j][half * 2 + 0] + beta, 0.f);
                u.T[rl * 132 + col + 1] = fmaxf(acc[i][j][half * 2 + 1] + beta, 0.f);
            }
        }
    }
    __syncthreads();
    if (my == 0) {
        // rows 0-31: f (pooled); rows 32-63: g (copy)
        {
            int n = t & 31, cb = (t >> 5) * 4;
#pragma unroll
            for (int cc = 0; cc < 4; cc++) {
                int c = cb + cc;
                const float* r0 = &u.T[c * 132 + 2 * n];
                float v = fmaxf(fmaxf(r0[0], r0[1]), fmaxf(r0[64], r0[65]));
                g_f[(size_t)(b * 32 + c) * 1024 + bx * 32 + n] = v;
            }
        }
#pragma unroll
        for (int p = 0; p < 4; p++) {
            int slot = t + p * 256, r = slot >> 5, c4 = (slot & 31) * 4;
            float4 v = *(const float4*)&u.T[(32 + r) * 132 + c4];
            *(float4*)&g_gm[((size_t)(b * 32 + r) << 12) + p0 + c4] = v;
        }
    } else {
        // 64 hh channels (c_global0 = (my-1)*64), pooled + transposed into g_hh[b][n][c]
        const int cg0 = (my - 1) * 64;
        int n = t & 31, cb = (t >> 5) * 8;
        float vals[8];
#pragma unroll
        for (int cc = 0; cc < 8; cc++) {
            int c = cb + cc;
            const float* r0 = &u.T[c * 132 + 2 * n];
            vals[cc] = fmaxf(fmaxf(r0[0], r0[1]), fmaxf(r0[64], r0[65]));
        }
        float* dst = &g_hh[(size_t)(b * 1024 + bx * 32 + n) * 128 + cg0 + cb];
        *(float4*)dst       = make_float4(vals[0], vals[1], vals[2], vals[3]);
        *(float4*)(dst + 4) = make_float4(vals[4], vals[5], vals[6], vals[7]);
    }
}

// =====================================================================
// fused attention: per (b, 128-wide m tile):
//   loop n-tiles (64): s = f^T g (K=32); P = 2^s; rowsum += colsum(P);
//                      o += hh^T P (K=64)
//   epilogue: o /= rowsum -> g_o[b][c][m]
// dynamic smem: Bs_g 17408 | As_hh 34816 | U(f/P) 34816 | rowsum 512
// =====================================================================
__global__ __launch_bounds__(256) void fused_attn_kernel()
{
    extern __shared__ __align__(16) char dsm[];
    unsigned* Bsg = (unsigned*)dsm;                  // g [k=32][m=128+8]
    unsigned* Ahh = (unsigned*)(dsm + 17408);        // hh [n=64][c=128+8]
    unsigned* U   = (unsigned*)(dsm + 52224);        // f [k=32][n=64+8] then P [n=64][m=128+8]
    float* rowsum = (float*)(dsm + 87040);
    const int b = blockIdx.y, m0 = blockIdx.x * 128;
    const int t = threadIdx.x, lane = t & 31, w = t >> 5;
    const int g = lane >> 2, tig = lane & 3;
    const int mBaseS = (w >> 2) * 32, nBaseS = (w & 3) * 32;   // GEMM1: n x m
    const int mBaseO = (w >> 2) * 64, nBaseO = (w & 3) * 32;   // GEMM2: c x m
    if (t < 128) rowsum[t] = 0.f;

    // stage g once
    const float* gb = g_gm + (size_t)b * 32 * 4096;
#pragma unroll
    for (int p = 0; p < 2; p++) {
        int slot = t + p * 256, r = slot >> 5, c4 = (slot & 31) * 4;
        float4 v = *(const float4*)&gb[(size_t)r * 4096 + m0 + c4];
        unsigned* d = &Bsg[r * 136 + c4];
        d[0] = tf32r(v.x); d[1] = tf32r(v.y); d[2] = tf32r(v.z); d[3] = tf32r(v.w);
    }
    const float* fb  = g_f  + (size_t)b * 32 * 1024;
    const float* hhb = g_hh + (size_t)b * 1024 * 128;

    float acc_s[2][4][4] = {};
    float acc_o[4][4][4] = {};
    float esum[4][2] = {};

    for (int nt = 0; nt < 16; nt++) {
        const int n0 = nt * 64;
        __syncthreads();   // U (P) + Ahh consumed by previous GEMM2; g staged (first iter)
        // stage f tile [32][64] into U
#pragma unroll
        for (int p = 0; p < 2; p++) {
            int slot = t + p * 256, r = slot >> 4, c4 = (slot & 15) * 4;
            float4 v = *(const float4*)&fb[r * 1024 + n0 + c4];
            unsigned* d = &U[r * 72 + c4];
            d[0] = tf32r(v.x); d[1] = tf32r(v.y); d[2] = tf32r(v.z); d[3] = tf32r(v.w);
        }
        // stage hh tile [64][128] into Ahh
#pragma unroll
        for (int p = 0; p < 8; p++) {
            int slot = t + p * 256, r = slot >> 5, c4 = (slot & 31) * 4;
            float4 v = *(const float4*)&hhb[(size_t)(n0 + r) * 128 + c4];
            unsigned* d = &Ahh[r * 136 + c4];
            d[0] = tf32r(v.x); d[1] = tf32r(v.y); d[2] = tf32r(v.z); d[3] = tf32r(v.w);
        }
        __syncthreads();
        // GEMM1: s[n 64][m 128], K=32
        mma_ktile<2, 4, 72, 136>(U, Bsg, mBaseS, nBaseS, g, tig, acc_s);
        __syncthreads();   // all GEMM1 reads of U(f) done before P overwrites
        // exp -> P, accumulate column sums, clear acc_s
#pragma unroll
        for (int i = 0; i < 2; i++) {
            int row = mBaseS + i * 16 + g;
#pragma unroll
            for (int j = 0; j < 4; j++) {
                int col = nBaseS + j * 8 + 2 * tig;
                float e0 = ex2f(acc_s[i][j][0]);
                float e1 = ex2f(acc_s[i][j][1]);
                float e2 = ex2f(acc_s[i][j][2]);
                float e3 = ex2f(acc_s[i][j][3]);
                esum[j][0] += e0 + e2;
                esum[j][1] += e1 + e3;
                U[row * 136 + col]           = tf32r(e0);
                U[row * 136 + col + 1]       = tf32r(e1);
                U[(row + 8) * 136 + col]     = tf32r(e2);
                U[(row + 8) * 136 + col + 1] = tf32r(e3);
                acc_s[i][j][0] = 0.f; acc_s[i][j][1] = 0.f;
                acc_s[i][j][2] = 0.f; acc_s[i][j][3] = 0.f;
            }
        }
        __syncthreads();
        // GEMM2: o[c 128][m 128] += hh^T P, K=64
        mma_ktile<4, 4, 136, 136>(Ahh, U, mBaseO, nBaseO, g, tig, acc_o);
        mma_ktile<4, 4, 136, 136>(Ahh + 32 * 136, U + 32 * 136, mBaseO, nBaseO, g, tig, acc_o);
    }
    // rowsum reduce (two warp-rows share m columns)
#pragma unroll
    for (int j = 0; j < 4; j++) {
        int col = nBaseO + j * 8 + 2 * tig;
        atomicAdd(&rowsum[col],     esum[j][0]);
        atomicAdd(&rowsum[col + 1], esum[j][1]);
    }
    __syncthreads();
    float* ob = g_o + (size_t)b * 128 * 4096;
#pragma unroll
    for (int j = 0; j < 4; j++) {
        int col = nBaseO + j * 8 + 2 * tig;
        float inv0 = 1.f / rowsum[col], inv1 = 1.f / rowsum[col + 1];
#pragma unroll
        for (int i = 0; i < 4; i++) {
            int row = mBaseO + i * 16 + g;
            *(float2*)&ob[(size_t)row * 4096 + m0 + col] =
                make_float2(acc_o[i][j][0] * inv0, acc_o[i][j][1] * inv1);
            *(float2*)&ob[(size_t)(row + 8) * 4096 + m0 + col] =
                make_float2(acc_o[i][j][2] * inv0, acc_o[i][j][3] * inv1);
        }
    }
}

// =====================================================================
// final: out = conv4'(o) + gbeta + x  (gamma/alpha folded into w4T)
// M=256, K=128, N=4096 per b. BM=128, BN=128. grid (32, 2, NB)
// =====================================================================
__global__ __launch_bounds__(256) void final_mma_kernel(const float* __restrict__ x,
                                                        float* __restrict__ out)
{
    __shared__ unsigned As[32 * 136];
    __shared__ unsigned Bs[32 * 136];
    const int b = blockIdx.z;
    const int m0 = blockIdx.y * 128, p0 = blockIdx.x * 128;
    const int t = threadIdx.x, lane = t & 31, w = t >> 5;
    const int g = lane >> 2, tig = lane & 3;
    const int mBase = (w >> 2) * 64, nBase = (w & 3) * 32;
    const float* ob = g_o + (size_t)b * 128 * 4096;
    float acc[4][4][4] = {};
    for (int kt = 0; kt < 4; kt++) {
        const int k0 = kt * 32;
#pragma unroll
        for (int p = 0; p < 4; p++) {
            int slot = t + p * 256, r = slot >> 5, c4 = (slot & 31) * 4;
            float4 v = *(const float4*)&g_w4T[(k0 + r) * 256 + m0 + c4];
            unsigned* d = &As[r * 136 + c4];
            d[0] = tf32r(v.x); d[1] = tf32r(v.y); d[2] = tf32r(v.z); d[3] = tf32r(v.w);
            float4 uu = *(const float4*)&ob[(size_t)(k0 + r) * 4096 + p0 + c4];
            unsigned* e = &Bs[r * 136 + c4];
            e[0] = tf32r(uu.x); e[1] = tf32r(uu.y); e[2] = tf32r(uu.z); e[3] = tf32r(uu.w);
        }
        __syncthreads();
        mma_ktile<4, 4, 136, 136>(As, Bs, mBase, nBase, g, tig, acc);
        __syncthreads();
    }
#pragma unroll
    for (int i = 0; i < 4; i++) {
#pragma unroll
        for (int half = 0; half < 2; half++) {
            int r = m0 + mBase + i * 16 + g + half * 8;
            float gb = g_ab4[256 + r];
            size_t base = ((size_t)(b * 256 + r) << 12) + p0;
#pragma unroll
            for (int j = 0; j < 4; j++) {
                int col = nBase + j * 8 + 2 * tig;
                float2 xv = *(const float2*)&x[base + col];
                float2 o;
                o.x = acc[i][j][half * 2 + 0] + gb + xv.x;
                o.y = acc[i][j][half * 2 + 1] + gb + xv.y;
                *(float2*)&out[base + col] = o;
            }
        }
    }
}

// =====================================================================
extern "C" void kernel_launch(void* const* d_in, const int* in_sizes, int n_in,
                              void* d_out, int out_size)
{
    const float* x  = (const float*)d_in[0];
    const float* w1 = (const float*)d_in[1],  *b1 = (const float*)d_in[2],
               * s1 = (const float*)d_in[3],  *t1 = (const float*)d_in[4],
               * m1 = (const float*)d_in[5],  *v1 = (const float*)d_in[6];
    const float* w2 = (const float*)d_in[7],  *b2 = (const float*)d_in[8],
               * s2 = (const float*)d_in[9],  *t2 = (const float*)d_in[10],
               * m2 = (const float*)d_in[11], *v2 = (const float*)d_in[12];
    const float* w3 = (const float*)d_in[13], *b3 = (const float*)d_in[14],
               * s3 = (const float*)d_in[15], *t3 = (const float*)d_in[16],
               * m3 = (const float*)d_in[17], *v3 = (const float*)d_in[18];
    const float* w4 = (const float*)d_in[19], *b4 = (const float*)d_in[20],
               * s4 = (const float*)d_in[21], *t4 = (const float*)d_in[22],
               * m4 = (const float*)d_in[23], *v4 = (const float*)d_in[24];
    const float* gamma = (const float*)d_in[25];
    float* out = (float*)d_out;

    cudaFuncSetAttribute(fused_attn_kernel,
                         cudaFuncAttributeMaxDynamicSharedMemorySize, 90112);

    pre_kernel<<<322, 256>>>(w1, w2, w3, w4,
                             b1, s1, t1, m1, v1,
                             b2, s2, t2, m2, v2,
                             b3, s3, t3, m3, v3,
                             b4, s4, t4, m4, v4, gamma);

    proj_pool_kernel<<<dim3(32, 3, NB), 256>>>(x);

    fused_attn_kernel<<<dim3(32, NB), 256, 87552>>>();

    final_mma_kernel<<<dim3(32, 2, NB), 256>>>(x, out);
}

// round 6
// speedup vs baseline: 5.3758x; 1.5042x over previous
#include <cuda_runtime.h>
#include <cuda_bf16.h>
#include <math.h>

#define NB 8
#define NC 256
#define HWF 4096
#define HW4 1024
#define EPSV 1e-5f
#define LOG2E 1.4426950408889634f

// ---------------- scratch (static __device__, no allocation) ----------------
__device__ unsigned g_wTpp[128 * 192];           // proj wT bf16 k-pair packed [k2=128][m=192], alpha-folded
__device__ unsigned g_w4p [64 * 256];            // w4T bf16 packed [k2=64][m=256], gamma*alpha4 folded
__device__ float    g_abp[2 * 192];              // proj beta
__device__ float    g_ab4[2 * 256];              // final gamma*beta4 in [256..]
__device__ unsigned g_fp [NB * 16 * HW4];        // f bf16 packed  [b][k2=16][n]  (log2e folded)
__device__ unsigned g_gp [NB * 16 * HWF];        // g bf16 packed  [b][k2=16][m]
__device__ unsigned g_hhp[NB * 512 * 128];       // hh bf16 packed [b][n2=512][c=128]
__device__ float    g_o  [NB * 128 * HWF];       // attention out fp32 [b][c][m]

// ---------------- helpers ----------------
__device__ __forceinline__ unsigned packbf(float a, float b) {
    __nv_bfloat162 t = __floats2bfloat162_rn(a, b);   // .x(lo)=a, .y(hi)=b
    return *(unsigned*)&t;
}
__device__ __forceinline__ float ex2f(float f) {
    float r; asm("ex2.approx.ftz.f32 %0, %1;" : "=f"(r) : "f"(f)); return r;
}
__device__ __forceinline__ void mma16(float* d, const unsigned* a, const unsigned* b) {
    asm volatile(
        "mma.sync.aligned.m16n8k16.row.col.f32.bf16.bf16.f32 "
        "{%0,%1,%2,%3},{%4,%5,%6,%7},{%8,%9},{%0,%1,%2,%3};"
        : "+f"(d[0]), "+f"(d[1]), "+f"(d[2]), "+f"(d[3])
        : "r"(a[0]), "r"(a[1]), "r"(a[2]), "r"(a[3]), "r"(b[0]), "r"(b[1]));
}

// one 32-deep (real k) tile = 16 packed rows. As[k2][m] stride AS, Bs[k2][n] stride BS.
template<int MF, int NF, int AS, int BS>
__device__ __forceinline__ void mma_ktile(const unsigned* As, const unsigned* Bs,
                                          int mBase, int nBase, int g, int tig,
                                          float (*acc)[NF][4])
{
#pragma unroll
    for (int ks = 0; ks < 2; ks++) {
        unsigned a[MF][4], b[NF][2];
        const unsigned* Ap = As + (ks * 8 + tig) * AS;
        const unsigned* Bp = Bs + (ks * 8 + tig) * BS;
#pragma unroll
        for (int i = 0; i < MF; i++) {
            const unsigned* p = Ap + mBase + i * 16 + g;
            a[i][0] = p[0]; a[i][1] = p[8];
            a[i][2] = p[4 * AS]; a[i][3] = p[4 * AS + 8];
        }
#pragma unroll
        for (int j = 0; j < NF; j++) {
            const unsigned* p = Bp + nBase + j * 8 + g;
            b[j][0] = p[0]; b[j][1] = p[4 * BS];
        }
#pragma unroll
        for (int i = 0; i < MF; i++)
#pragma unroll
            for (int j = 0; j < NF; j++)
                mma16(acc[i][j], a[i], b[j]);
    }
}

// =====================================================================
// pre: bf16 k-pair-packed transposed weights (alpha folded), beta vectors
// =====================================================================
__global__ void pre_kernel(const float* __restrict__ w1, const float* __restrict__ w2,
                           const float* __restrict__ w3, const float* __restrict__ w4,
                           const float* __restrict__ b1, const float* __restrict__ s1,
                           const float* __restrict__ t1, const float* __restrict__ m1,
                           const float* __restrict__ v1,
                           const float* __restrict__ b2, const float* __restrict__ s2,
                           const float* __restrict__ t2, const float* __restrict__ m2,
                           const float* __restrict__ v2,
                           const float* __restrict__ b3, const float* __restrict__ s3,
                           const float* __restrict__ t3, const float* __restrict__ m3,
                           const float* __restrict__ v3,
                           const float* __restrict__ b4, const float* __restrict__ s4,
                           const float* __restrict__ t4, const float* __restrict__ m4,
                           const float* __restrict__ v4,
                           const float* __restrict__ gamma)
{
    int idx = blockIdx.x * 256 + threadIdx.x;
    if (idx < 24576) {                       // wTpp: pack w(2k2,m), w(2k2+1,m) with alpha folded
        int k2 = idx / 192, m = idx % 192;
        float alpha;
        float v0, v1_;
        if (m < 32)      { alpha = s1[m] * rsqrtf(v1[m] + EPSV) * LOG2E;
                           v0 = w1[m * 256 + 2 * k2]; v1_ = w1[m * 256 + 2 * k2 + 1]; }
        else if (m < 64) { alpha = s2[m - 32] * rsqrtf(v2[m - 32] + EPSV);
                           v0 = w2[(m - 32) * 256 + 2 * k2]; v1_ = w2[(m - 32) * 256 + 2 * k2 + 1]; }
        else             { alpha = s3[m - 64] * rsqrtf(v3[m - 64] + EPSV);
                           v0 = w3[(m - 64) * 256 + 2 * k2]; v1_ = w3[(m - 64) * 256 + 2 * k2 + 1]; }
        g_wTpp[idx] = packbf(v0 * alpha, v1_ * alpha);
        return;
    }
    idx -= 24576;
    if (idx < 16384) {                       // w4p
        int k2 = idx / 256, m = idx % 256;
        float alpha = s4[m] * rsqrtf(v4[m] + EPSV) * gamma[0];
        g_w4p[idx] = packbf(w4[m * 128 + 2 * k2] * alpha, w4[m * 128 + 2 * k2 + 1] * alpha);
        return;
    }
    idx -= 16384;
    if (idx < 192) {
        int r = idx;
        float bb, ss, tt, mm, vv, lg = 1.f;
        if (r < 32)      { bb = b1[r];      ss = s1[r];      tt = t1[r];      mm = m1[r];      vv = v1[r]; lg = LOG2E; }
        else if (r < 64) { bb = b2[r - 32]; ss = s2[r - 32]; tt = t2[r - 32]; mm = m2[r - 32]; vv = v2[r - 32]; }
        else             { bb = b3[r - 64]; ss = s3[r - 64]; tt = t3[r - 64]; mm = m3[r - 64]; vv = v3[r - 64]; }
        float alpha = ss * rsqrtf(vv + EPSV);
        g_abp[192 + r] = fmaf(bb - mm, alpha, tt) * lg;
        return;
    }
    idx -= 192;
    if (idx < 256) {
        int r = idx;
        float alpha = s4[r] * rsqrtf(v4[r] + EPSV);
        g_ab4[256 + r] = fmaf(b4[r] - m4[r], alpha, t4[r]) * gamma[0];
    }
}

// =====================================================================
// proj+pool: GEMM(M=64 slice, K=256, N=128) + BN + ReLU, then pool+route.
// grid (32 p-tiles, 3 m-slices, NB), 256 threads.
// =====================================================================
__global__ __launch_bounds__(256) void proj_pool_kernel(const float* __restrict__ x)
{
    __shared__ union {
        struct { unsigned As[16 * 72]; unsigned Bs[16 * 136]; } s;
        float T[64 * 132];
    } u;
    const int b = blockIdx.z;
    const int my = blockIdx.y, m0 = my * 64;
    const int bx = blockIdx.x, p0 = bx * 128;
    const int t = threadIdx.x, lane = t & 31, w = t >> 5;
    const int g = lane >> 2, tig = lane & 3;
    const int mBase = (w >> 2) * 32, nBase = (w & 3) * 32;
    const float* xb = x + ((size_t)b << 20);
    float acc[2][4][4] = {};
    for (int kt = 0; kt < 8; kt++) {
        const int k0 = kt * 32;
        // A: wTpp packed rows [kt*16 .. +16][m0:64] — direct copy
        {
            int r = t >> 4, c4 = (t & 15) * 4;
            *(uint4*)&u.s.As[r * 72 + c4] =
                *(const uint4*)&g_wTpp[(kt * 16 + r) * 192 + m0 + c4];
        }
        // B: x rows k0+2r, k0+2r+1 packed
#pragma unroll
        for (int p = 0; p < 2; p++) {
            int slot = t + p * 256, r = slot >> 5, c4 = (slot & 31) * 4;
            float4 va = *(const float4*)&xb[((size_t)(k0 + 2 * r) << 12) + p0 + c4];
            float4 vb = *(const float4*)&xb[((size_t)(k0 + 2 * r + 1) << 12) + p0 + c4];
            unsigned* d = &u.s.Bs[r * 136 + c4];
            d[0] = packbf(va.x, vb.x); d[1] = packbf(va.y, vb.y);
            d[2] = packbf(va.z, vb.z); d[3] = packbf(va.w, vb.w);
        }
        __syncthreads();
        mma_ktile<2, 4, 72, 136>(u.s.As, u.s.Bs, mBase, nBase, g, tig, acc);
        __syncthreads();
    }
    // BN + ReLU into smem tile T[m 64][p 128] (stride 132)
#pragma unroll
    for (int i = 0; i < 2; i++) {
#pragma unroll
        for (int half = 0; half < 2; half++) {
            int rl = mBase + i * 16 + g + half * 8;
            float beta = g_abp[192 + m0 + rl];
#pragma unroll
            for (int j = 0; j < 4; j++) {
                int col = nBase + j * 8 + 2 * tig;
                u.T[rl * 132 + col]     = fmaxf(acc[i][j][half * 2 + 0] + beta, 0.f);
                u.T[rl * 132 + col + 1] = fmaxf(acc[i][j][half * 2 + 1] + beta, 0.f);
            }
        }
    }
    __syncthreads();
    if (my == 0) {
        // rows 0-31: f (pooled, packed channel pairs)
        {
            int n = t & 31, cb = (t >> 5) * 4;
            float vals[4];
#pragma unroll
            for (int cc = 0; cc < 4; cc++) {
                const float* r0 = &u.T[(cb + cc) * 132 + 2 * n];
                vals[cc] = fmaxf(fmaxf(r0[0], r0[1]), fmaxf(r0[64], r0[65]));
            }
            int r2 = cb >> 1;
            g_fp[(size_t)(b * 16 + r2)     * 1024 + bx * 32 + n] = packbf(vals[0], vals[1]);
            g_fp[(size_t)(b * 16 + r2 + 1) * 1024 + bx * 32 + n] = packbf(vals[2], vals[3]);
        }
        // rows 32-63: g (packed channel pairs)
#pragma unroll
        for (int p = 0; p < 2; p++) {
            int slot = t + p * 256, r = slot >> 5, c4 = (slot & 31) * 4;
            const float* ra = &u.T[(32 + 2 * r) * 132 + c4];
            const float* rb = &u.T[(32 + 2 * r + 1) * 132 + c4];
            uint4 o;
            o.x = packbf(ra[0], rb[0]); o.y = packbf(ra[1], rb[1]);
            o.z = packbf(ra[2], rb[2]); o.w = packbf(ra[3], rb[3]);
            *(uint4*)&g_gp[(((size_t)(b * 16 + r)) << 12) + p0 + c4] = o;
        }
    } else {
        // 64 hh channels, pooled + transposed + n-pair packed: g_hhp[b][n2][c]
        const int cg0 = (my - 1) * 64;
        int n2l = t & 15, cb = (t >> 4) * 4;
        unsigned pk[4];
#pragma unroll
        for (int cc = 0; cc < 4; cc++) {
            const float* r0 = &u.T[(cb + cc) * 132 + 4 * n2l];
            float v0 = fmaxf(fmaxf(r0[0], r0[1]), fmaxf(r0[64], r0[65]));
            float v1 = fmaxf(fmaxf(r0[2], r0[3]), fmaxf(r0[66], r0[67]));
            pk[cc] = packbf(v0, v1);
        }
        *(uint4*)&g_hhp[(size_t)(b * 512 + bx * 16 + n2l) * 128 + cg0 + cb] =
            make_uint4(pk[0], pk[1], pk[2], pk[3]);
    }
}

// =====================================================================
// fused attention per (b, 128-m tile):
//   nt loop (64 n): s = f^T g (K=32) -> P = 2^s (16-bit interleaved smem)
//                   -> o += hh^T P (K=64); rowsum accumulated
// smem: Bsg 16x136 (8704) | Ahh 32x136 (17408) | U 32x136 (17408) | rowsum 512
// =====================================================================
__global__ __launch_bounds__(256) void fused_attn_kernel()
{
    extern __shared__ __align__(16) char dsm[];
    unsigned* Bsg = (unsigned*)dsm;                  // g packed [k2=16][m 128+8]
    unsigned* Ahh = (unsigned*)(dsm + 8704);         // hh packed [n2=32][c 128+8]
    unsigned* U   = (unsigned*)(dsm + 26112);        // f packed [16][64+8] then P packed [n2=32][m 128+8]
    float* rowsum = (float*)(dsm + 43520);
    __nv_bfloat16* U16 = (__nv_bfloat16*)U;
    const int b = blockIdx.y, m0 = blockIdx.x * 128;
    const int t = threadIdx.x, lane = t & 31, w = t >> 5;
    const int g = lane >> 2, tig = lane & 3;
    const int mBaseS = (w >> 2) * 32, nBaseS = (w & 3) * 32;   // GEMM1: n x m
    const int mBaseO = (w >> 2) * 64, nBaseO = (w & 3) * 32;   // GEMM2: c x m
    if (t < 128) rowsum[t] = 0.f;

    // stage g once (direct packed copy)
#pragma unroll
    for (int p = 0; p < 2; p++) {
        int slot = t + p * 256, r = slot >> 5, c4 = (slot & 31) * 4;
        *(uint4*)&Bsg[r * 136 + c4] =
            *(const uint4*)&g_gp[(((size_t)(b * 16 + r)) << 12) + m0 + c4];
    }
    const unsigned* fb  = g_fp  + (size_t)b * 16 * 1024;
    const unsigned* hhb = g_hhp + (size_t)b * 512 * 128;

    float acc_s[2][4][4] = {};
    float acc_o[4][4][4] = {};
    float esum[4][2] = {};

    for (int nt = 0; nt < 16; nt++) {
        __syncthreads();   // previous GEMM2 done with U/Ahh; g staged (first iter)
        // stage f tile packed [16][64] into U
        {
            int r = t >> 4, c4 = (t & 15) * 4;
            *(uint4*)&U[r * 72 + c4] = *(const uint4*)&fb[r * 1024 + nt * 64 + c4];
        }
        // stage hh tile packed [32][128] into Ahh
#pragma unroll
        for (int p = 0; p < 4; p++) {
            int slot = t + p * 256, r = slot >> 5, c4 = (slot & 31) * 4;
            *(uint4*)&Ahh[r * 136 + c4] =
                *(const uint4*)&hhb[(size_t)(nt * 32 + r) * 128 + c4];
        }
        __syncthreads();
        // GEMM1: s[n 64][m 128], K=32
        mma_ktile<2, 4, 72, 136>(U, Bsg, mBaseS, nBaseS, g, tig, acc_s);
        __syncthreads();   // all GEMM1 reads of U(f) done before P overwrites
        // exp -> P (16-bit interleaved: addr16 = (n>>1)*272 + m*2 + (n&1))
#pragma unroll
        for (int i = 0; i < 2; i++) {
            int row = mBaseS + i * 16 + g;
            int r2a = (row >> 1) * 272 + (row & 1);
            int r2b = ((row + 8) >> 1) * 272 + (row & 1);
#pragma unroll
            for (int j = 0; j < 4; j++) {
                int col = nBaseS + j * 8 + 2 * tig;
                float e0 = ex2f(acc_s[i][j][0]);
                float e1 = ex2f(acc_s[i][j][1]);
                float e2 = ex2f(acc_s[i][j][2]);
                float e3 = ex2f(acc_s[i][j][3]);
                esum[j][0] += e0 + e2;
                esum[j][1] += e1 + e3;
                U16[r2a + col * 2]       = __float2bfloat16_rn(e0);
                U16[r2a + (col + 1) * 2] = __float2bfloat16_rn(e1);
                U16[r2b + col * 2]       = __float2bfloat16_rn(e2);
                U16[r2b + (col + 1) * 2] = __float2bfloat16_rn(e3);
                acc_s[i][j][0] = 0.f; acc_s[i][j][1] = 0.f;
                acc_s[i][j][2] = 0.f; acc_s[i][j][3] = 0.f;
            }
        }
        __syncthreads();
        // GEMM2: o[c 128][m 128] += hh^T P, K=64 (32 packed rows = 2 ktiles)
        mma_ktile<4, 4, 136, 136>(Ahh,            U,            mBaseO, nBaseO, g, tig, acc_o);
        mma_ktile<4, 4, 136, 136>(Ahh + 16 * 136, U + 16 * 136, mBaseO, nBaseO, g, tig, acc_o);
    }
#pragma unroll
    for (int j = 0; j < 4; j++) {
        int col = nBaseO + j * 8 + 2 * tig;
        atomicAdd(&rowsum[col],     esum[j][0]);
        atomicAdd(&rowsum[col + 1], esum[j][1]);
    }
    __syncthreads();
    float* ob = g_o + (size_t)b * 128 * 4096;
#pragma unroll
    for (int j = 0; j < 4; j++) {
        int col = nBaseO + j * 8 + 2 * tig;
        float inv0 = 1.f / rowsum[col], inv1 = 1.f / rowsum[col + 1];
#pragma unroll
        for (int i = 0; i < 4; i++) {
            int row = mBaseO + i * 16 + g;
            *(float2*)&ob[(size_t)row * 4096 + m0 + col] =
                make_float2(acc_o[i][j][0] * inv0, acc_o[i][j][1] * inv1);
            *(float2*)&ob[(size_t)(row + 8) * 4096 + m0 + col] =
                make_float2(acc_o[i][j][2] * inv0, acc_o[i][j][3] * inv1);
        }
    }
}

// =====================================================================
// final: out = conv4'(o) + gbeta + x. M=256, K=128, N=4096/b. grid (32,2,NB)
// =====================================================================
__global__ __launch_bounds__(256) void final_mma_kernel(const float* __restrict__ x,
                                                        float* __restrict__ out)
{
    __shared__ unsigned As[16 * 136];
    __shared__ unsigned Bs[16 * 136];
    const int b = blockIdx.z;
    const int m0 = blockIdx.y * 128, p0 = blockIdx.x * 128;
    const int t = threadIdx.x, lane = t & 31, w = t >> 5;
    const int g = lane >> 2, tig = lane & 3;
    const int mBase = (w >> 2) * 64, nBase = (w & 3) * 32;
    const float* ob = g_o + (size_t)b * 128 * 4096;
    float acc[4][4][4] = {};
    for (int kt = 0; kt < 4; kt++) {
        const int k0 = kt * 32;
#pragma unroll
        for (int p = 0; p < 2; p++) {
            int slot = t + p * 256, r = slot >> 5, c4 = (slot & 31) * 4;
            *(uint4*)&As[r * 136 + c4] =
                *(const uint4*)&g_w4p[(kt * 16 + r) * 256 + m0 + c4];
            float4 va = *(const float4*)&ob[(size_t)(k0 + 2 * r) * 4096 + p0 + c4];
            float4 vb = *(const float4*)&ob[(size_t)(k0 + 2 * r + 1) * 4096 + p0 + c4];
            unsigned* e = &Bs[r * 136 + c4];
            e[0] = packbf(va.x, vb.x); e[1] = packbf(va.y, vb.y);
            e[2] = packbf(va.z, vb.z); e[3] = packbf(va.w, vb.w);
        }
        __syncthreads();
        mma_ktile<4, 4, 136, 136>(As, Bs, mBase, nBase, g, tig, acc);
        __syncthreads();
    }
#pragma unroll
    for (int i = 0; i < 4; i++) {
#pragma unroll
        for (int half = 0; half < 2; half++) {
            int r = m0 + mBase + i * 16 + g + half * 8;
            float gb = g_ab4[256 + r];
            size_t base = ((size_t)(b * 256 + r) << 12) + p0;
#pragma unroll
            for (int j = 0; j < 4; j++) {
                int col = nBase + j * 8 + 2 * tig;
                float2 xv = *(const float2*)&x[base + col];
                float2 o;
                o.x = acc[i][j][half * 2 + 0] + gb + xv.x;
                o.y = acc[i][j][half * 2 + 1] + gb + xv.y;
                *(float2*)&out[base + col] = o;
            }
        }
    }
}

// =====================================================================
extern "C" void kernel_launch(void* const* d_in, const int* in_sizes, int n_in,
                              void* d_out, int out_size)
{
    const float* x  = (const float*)d_in[0];
    const float* w1 = (const float*)d_in[1],  *b1 = (const float*)d_in[2],
               * s1 = (const float*)d_in[3],  *t1 = (const float*)d_in[4],
               * m1 = (const float*)d_in[5],  *v1 = (const float*)d_in[6];
    const float* w2 = (const float*)d_in[7],  *b2 = (const float*)d_in[8],
               * s2 = (const float*)d_in[9],  *t2 = (const float*)d_in[10],
               * m2 = (const float*)d_in[11], *v2 = (const float*)d_in[12];
    const float* w3 = (const float*)d_in[13], *b3 = (const float*)d_in[14],
               * s3 = (const float*)d_in[15], *t3 = (const float*)d_in[16],
               * m3 = (const float*)d_in[17], *v3 = (const float*)d_in[18];
    const float* w4 = (const float*)d_in[19], *b4 = (const float*)d_in[20],
               * s4 = (const float*)d_in[21], *t4 = (const float*)d_in[22],
               * m4 = (const float*)d_in[23], *v4 = (const float*)d_in[24];
    const float* gamma = (const float*)d_in[25];
    float* out = (float*)d_out;

    cudaFuncSetAttribute(fused_attn_kernel,
                         cudaFuncAttributeMaxDynamicSharedMemorySize, 46080);

    pre_kernel<<<162, 256>>>(w1, w2, w3, w4,
                             b1, s1, t1, m1, v1,
                             b2, s2, t2, m2, v2,
                             b3, s3, t3, m3, v3,
                             b4, s4, t4, m4, v4, gamma);

    proj_pool_kernel<<<dim3(32, 3, NB), 256>>>(x);

    fused_attn_kernel<<<dim3(32, NB), 256, 44032>>>();

    final_mma_kernel<<<dim3(32, 2, NB), 256>>>(x, out);
}

// round 7
// speedup vs baseline: 5.8931x; 1.0962x over previous
#include <cuda_runtime.h>
#include <cuda_bf16.h>
#include <math.h>

#define NB 8
#define NC 256
#define HWF 4096
#define HW4 1024
#define EPSV 1e-5f
#define LOG2E 1.4426950408889634f

// ---------------- scratch (static __device__, no allocation) ----------------
__device__ unsigned g_wTpp[128 * 192];           // proj wT bf16 k-pair packed [k2=128][m=192], alpha-folded
__device__ unsigned g_w4p [64 * 256];            // w4T bf16 packed [k2=64][m=256]; k2=gi*8+g -> (gi*16+g, +8)
__device__ float    g_abp[2 * 192];              // proj beta
__device__ float    g_ab4[2 * 256];              // final gamma*beta4 in [256..]
__device__ unsigned g_fp [NB * 16 * HW4];        // f bf16 packed  [b][k2=16][n]  (log2e folded)
__device__ unsigned g_gp [NB * 16 * HWF];        // g bf16 packed  [b][k2=16][m]
__device__ unsigned g_hhp[NB * 512 * 128];       // hh bf16 packed [b][n2=512][c=128]
__device__ unsigned g_op [NB * 64 * HWF];        // o bf16 packed  [b][k2=64][m] (permuted pairs)

// ---------------- helpers ----------------
__device__ __forceinline__ unsigned packbf(float a, float b) {
    __nv_bfloat162 t = __floats2bfloat162_rn(a, b);   // .x(lo)=a, .y(hi)=b
    return *(unsigned*)&t;
}
__device__ __forceinline__ float ex2f(float f) {
    float r; asm("ex2.approx.ftz.f32 %0, %1;" : "=f"(r) : "f"(f)); return r;
}
__device__ __forceinline__ void cpa16(void* s, const void* g) {
    unsigned a = (unsigned)__cvta_generic_to_shared(s);
    asm volatile("cp.async.ca.shared.global [%0], [%1], 16;" :: "r"(a), "l"(g));
}
__device__ __forceinline__ void cp_commit() { asm volatile("cp.async.commit_group;"); }
template<int N> __device__ __forceinline__ void cp_wait() {
    asm volatile("cp.async.wait_group %0;" :: "n"(N));
}
__device__ __forceinline__ void mma16(float* d, const unsigned* a, const unsigned* b) {
    asm volatile(
        "mma.sync.aligned.m16n8k16.row.col.f32.bf16.bf16.f32 "
        "{%0,%1,%2,%3},{%4,%5,%6,%7},{%8,%9},{%0,%1,%2,%3};"
        : "+f"(d[0]), "+f"(d[1]), "+f"(d[2]), "+f"(d[3])
        : "r"(a[0]), "r"(a[1]), "r"(a[2]), "r"(a[3]), "r"(b[0]), "r"(b[1]));
}

// one 32-deep (real k) tile = 16 packed rows. As[k2][m] stride AS, Bs[k2][n] stride BS.
template<int MF, int NF, int AS, int BS>
__device__ __forceinline__ void mma_ktile(const unsigned* As, const unsigned* Bs,
                                          int mBase, int nBase, int g, int tig,
                                          float (*acc)[NF][4])
{
#pragma unroll
    for (int ks = 0; ks < 2; ks++) {
        unsigned a[MF][4], b[NF][2];
        const unsigned* Ap = As + (ks * 8 + tig) * AS;
        const unsigned* Bp = Bs + (ks * 8 + tig) * BS;
#pragma unroll
        for (int i = 0; i < MF; i++) {
            const unsigned* p = Ap + mBase + i * 16 + g;
            a[i][0] = p[0]; a[i][1] = p[8];
            a[i][2] = p[4 * AS]; a[i][3] = p[4 * AS + 8];
        }
#pragma unroll
        for (int j = 0; j < NF; j++) {
            const unsigned* p = Bp + nBase + j * 8 + g;
            b[j][0] = p[0]; b[j][1] = p[4 * BS];
        }
#pragma unroll
        for (int i = 0; i < MF; i++)
#pragma unroll
            for (int j = 0; j < NF; j++)
                mma16(acc[i][j], a[i], b[j]);
    }
}

// =====================================================================
// pre
// =====================================================================
__global__ void pre_kernel(const float* __restrict__ w1, const float* __restrict__ w2,
                           const float* __restrict__ w3, const float* __restrict__ w4,
                           const float* __restrict__ b1, const float* __restrict__ s1,
                           const float* __restrict__ t1, const float* __restrict__ m1,
                           const float* __restrict__ v1,
                           const float* __restrict__ b2, const float* __restrict__ s2,
                           const float* __restrict__ t2, const float* __restrict__ m2,
                           const float* __restrict__ v2,
                           const float* __restrict__ b3, const float* __restrict__ s3,
                           const float* __restrict__ t3, const float* __restrict__ m3,
                           const float* __restrict__ v3,
                           const float* __restrict__ b4, const float* __restrict__ s4,
                           const float* __restrict__ t4, const float* __restrict__ m4,
                           const float* __restrict__ v4,
                           const float* __restrict__ gamma)
{
    int idx = blockIdx.x * 256 + threadIdx.x;
    if (idx < 24576) {                       // wTpp
        int k2 = idx / 192, m = idx % 192;
        float alpha, v0, v1_;
        if (m < 32)      { alpha = s1[m] * rsqrtf(v1[m] + EPSV) * LOG2E;
                           v0 = w1[m * 256 + 2 * k2]; v1_ = w1[m * 256 + 2 * k2 + 1]; }
        else if (m < 64) { alpha = s2[m - 32] * rsqrtf(v2[m - 32] + EPSV);
                           v0 = w2[(m - 32) * 256 + 2 * k2]; v1_ = w2[(m - 32) * 256 + 2 * k2 + 1]; }
        else             { alpha = s3[m - 64] * rsqrtf(v3[m - 64] + EPSV);
                           v0 = w3[(m - 64) * 256 + 2 * k2]; v1_ = w3[(m - 64) * 256 + 2 * k2 + 1]; }
        g_wTpp[idx] = packbf(v0 * alpha, v1_ * alpha);
        return;
    }
    idx -= 24576;
    if (idx < 16384) {                       // w4p, permuted pairs (gi*16+g, gi*16+g+8)
        int k2 = idx / 256, m = idx % 256;
        int gi = k2 >> 3, gg = k2 & 7;
        int lo = gi * 16 + gg, hi = lo + 8;
        float alpha = s4[m] * rsqrtf(v4[m] + EPSV) * gamma[0];
        g_w4p[idx] = packbf(w4[m * 128 + lo] * alpha, w4[m * 128 + hi] * alpha);
        return;
    }
    idx -= 16384;
    if (idx < 192) {
        int r = idx;
        float bb, ss, tt, mm, vv, lg = 1.f;
        if (r < 32)      { bb = b1[r];      ss = s1[r];      tt = t1[r];      mm = m1[r];      vv = v1[r]; lg = LOG2E; }
        else if (r < 64) { bb = b2[r - 32]; ss = s2[r - 32]; tt = t2[r - 32]; mm = m2[r - 32]; vv = v2[r - 32]; }
        else             { bb = b3[r - 64]; ss = s3[r - 64]; tt = t3[r - 64]; mm = m3[r - 64]; vv = v3[r - 64]; }
        float alpha = ss * rsqrtf(vv + EPSV);
        g_abp[192 + r] = fmaf(bb - mm, alpha, tt) * lg;
        return;
    }
    idx -= 192;
    if (idx < 256) {
        int r = idx;
        float alpha = s4[r] * rsqrtf(v4[r] + EPSV);
        g_ab4[256 + r] = fmaf(b4[r] - m4[r], alpha, t4[r]) * gamma[0];
    }
}

// =====================================================================
// proj+pool with register prefetch across k-tiles
// =====================================================================
__global__ __launch_bounds__(256) void proj_pool_kernel(const float* __restrict__ x)
{
    __shared__ union {
        struct { unsigned As[16 * 72]; unsigned Bs[16 * 136]; } s;
        float T[64 * 132];
    } u;
    const int b = blockIdx.z;
    const int my = blockIdx.y, m0 = my * 64;
    const int bx = blockIdx.x, p0 = bx * 128;
    const int t = threadIdx.x, lane = t & 31, w = t >> 5;
    const int g = lane >> 2, tig = lane & 3;
    const int mBase = (w >> 2) * 32, nBase = (w & 3) * 32;
    const float* xb = x + ((size_t)b << 20);
    const int arow = t >> 4, acol = (t & 15) * 4;
    float acc[2][4][4] = {};
    // prefetch kt=0
    uint4 wA = *(const uint4*)&g_wTpp[arow * 192 + m0 + acol];
    float4 va[2], vb[2];
#pragma unroll
    for (int p = 0; p < 2; p++) {
        int slot = t + p * 256, r = slot >> 5, c4 = (slot & 31) * 4;
        va[p] = *(const float4*)&xb[((size_t)(2 * r) << 12) + p0 + c4];
        vb[p] = *(const float4*)&xb[((size_t)(2 * r + 1) << 12) + p0 + c4];
    }
    for (int kt = 0; kt < 8; kt++) {
        *(uint4*)&u.s.As[arow * 72 + acol] = wA;
#pragma unroll
        for (int p = 0; p < 2; p++) {
            int slot = t + p * 256, r = slot >> 5, c4 = (slot & 31) * 4;
            unsigned* d = &u.s.Bs[r * 136 + c4];
            d[0] = packbf(va[p].x, vb[p].x); d[1] = packbf(va[p].y, vb[p].y);
            d[2] = packbf(va[p].z, vb[p].z); d[3] = packbf(va[p].w, vb[p].w);
        }
        __syncthreads();
        if (kt < 7) {
            const int k0 = (kt + 1) * 32;
            wA = *(const uint4*)&g_wTpp[((kt + 1) * 16 + arow) * 192 + m0 + acol];
#pragma unroll
            for (int p = 0; p < 2; p++) {
                int slot = t + p * 256, r = slot >> 5, c4 = (slot & 31) * 4;
                va[p] = *(const float4*)&xb[((size_t)(k0 + 2 * r) << 12) + p0 + c4];
                vb[p] = *(const float4*)&xb[((size_t)(k0 + 2 * r + 1) << 12) + p0 + c4];
            }
        }
        mma_ktile<2, 4, 72, 136>(u.s.As, u.s.Bs, mBase, nBase, g, tig, acc);
        __syncthreads();
    }
    // BN + ReLU into smem tile T[m 64][p 128]
#pragma unroll
    for (int i = 0; i < 2; i++) {
#pragma unroll
        for (int half = 0; half < 2; half++) {
            int rl = mBase + i * 16 + g + half * 8;
            float beta = g_abp[192 + m0 + rl];
#pragma unroll
            for (int j = 0; j < 4; j++) {
                int col = nBase + j * 8 + 2 * tig;
                u.T[rl * 132 + col]     = fmaxf(acc[i][j][half * 2 + 0] + beta, 0.f);
                u.T[rl * 132 + col + 1] = fmaxf(acc[i][j][half * 2 + 1] + beta, 0.f);
            }
        }
    }
    __syncthreads();
    if (my == 0) {
        {
            int n = t & 31, cb = (t >> 5) * 4;
            float vals[4];
#pragma unroll
            for (int cc = 0; cc < 4; cc++) {
                const float* r0 = &u.T[(cb + cc) * 132 + 2 * n];
                vals[cc] = fmaxf(fmaxf(r0[0], r0[1]), fmaxf(r0[64], r0[65]));
            }
            int r2 = cb >> 1;
            g_fp[(size_t)(b * 16 + r2)     * 1024 + bx * 32 + n] = packbf(vals[0], vals[1]);
            g_fp[(size_t)(b * 16 + r2 + 1) * 1024 + bx * 32 + n] = packbf(vals[2], vals[3]);
        }
#pragma unroll
        for (int p = 0; p < 2; p++) {
            int slot = t + p * 256, r = slot >> 5, c4 = (slot & 31) * 4;
            const float* ra = &u.T[(32 + 2 * r) * 132 + c4];
            const float* rb = &u.T[(32 + 2 * r + 1) * 132 + c4];
            uint4 o;
            o.x = packbf(ra[0], rb[0]); o.y = packbf(ra[1], rb[1]);
            o.z = packbf(ra[2], rb[2]); o.w = packbf(ra[3], rb[3]);
            *(uint4*)&g_gp[(((size_t)(b * 16 + r)) << 12) + p0 + c4] = o;
        }
    } else {
        const int cg0 = (my - 1) * 64;
        int n2l = t & 15, cb = (t >> 4) * 4;
        unsigned pk[4];
#pragma unroll
        for (int cc = 0; cc < 4; cc++) {
            const float* r0 = &u.T[(cb + cc) * 132 + 4 * n2l];
            float v0 = fmaxf(fmaxf(r0[0], r0[1]), fmaxf(r0[64], r0[65]));
            float v1 = fmaxf(fmaxf(r0[2], r0[3]), fmaxf(r0[66], r0[67]));
            pk[cc] = packbf(v0, v1);
        }
        *(uint4*)&g_hhp[(size_t)(b * 512 + bx * 16 + n2l) * 128 + cg0 + cb] =
            make_uint4(pk[0], pk[1], pk[2], pk[3]);
    }
}

// =====================================================================
// fused attention: BM(m)=64 per CTA, cp.async double-buffered f/hh tiles.
// smem: Bsg[16x72] | F[2][16x72] | H[2][32x136] | P[32x72] | rowsum[64]
// =====================================================================
__global__ __launch_bounds__(256, 2) void fused_attn_kernel()
{
    extern __shared__ __align__(16) char dsm[];
    unsigned* Bsg = (unsigned*)dsm;                      // 16x72
    unsigned* F   = (unsigned*)(dsm + 4608);             // 2 x 16x72
    unsigned* H   = (unsigned*)(dsm + 13824);            // 2 x 32x136
    unsigned* P   = (unsigned*)(dsm + 48640);            // 32x72 (16-bit interleaved)
    float* rowsum = (float*)(dsm + 57856);               // 64
    __nv_bfloat16* P16 = (__nv_bfloat16*)P;
    const int b = blockIdx.y, m0 = blockIdx.x * 64;
    const int t = threadIdx.x, lane = t & 31, w = t >> 5;
    const int g = lane >> 2, tig = lane & 3;
    const int mBaseS = (w >> 2) * 32, nBaseS = (w & 3) * 16;   // GEMM1: n x m
    const int mBaseO = (w >> 2) * 64, nBaseO = (w & 3) * 16;   // GEMM2: c x m
    if (t < 64) rowsum[t] = 0.f;

    // stage g once
    {
        int r = t >> 4, c4 = (t & 15) * 4;
        *(uint4*)&Bsg[r * 72 + c4] =
            *(const uint4*)&g_gp[(((size_t)(b * 16 + r)) << 12) + m0 + c4];
    }
    const unsigned* fb  = g_fp  + (size_t)b * 16 * 1024;
    const unsigned* hhb = g_hhp + (size_t)b * 512 * 128;

    const int fr = t >> 4, fs = t & 15;          // f tile: 16 rows x 16 segs
    // prologue: stage 0
    cpa16(&F[fr * 72 + fs * 4], &fb[fr * 1024 + fs * 4]);
#pragma unroll
    for (int p = 0; p < 4; p++) {
        int slot = t + p * 256, hr = slot >> 5, hs = slot & 31;
        cpa16(&H[hr * 136 + hs * 4], &hhb[hr * 128 + hs * 4]);
    }
    cp_commit();

    float acc_s[2][2][4] = {};
    float acc_o[4][2][4] = {};
    float esum[2][2] = {};

    for (int nt = 0; nt < 16; nt++) {
        cp_wait<0>();
        __syncthreads();                         // F/H[cur] ready; GEMM2(nt-1) done
        if (nt < 15) {
            const int bn = (nt + 1) & 1;
            cpa16(&F[bn * 1152 + fr * 72 + fs * 4], &fb[fr * 1024 + (nt + 1) * 64 + fs * 4]);
#pragma unroll
            for (int p = 0; p < 4; p++) {
                int slot = t + p * 256, hr = slot >> 5, hs = slot & 31;
                cpa16(&H[bn * 4352 + hr * 136 + hs * 4],
                      &hhb[(size_t)((nt + 1) * 32 + hr) * 128 + hs * 4]);
            }
            cp_commit();
        }
        const unsigned* Fc = F + (nt & 1) * 1152;
        const unsigned* Hc = H + (nt & 1) * 4352;
        // GEMM1: s[n 64][m 64], K=32
        mma_ktile<2, 2, 72, 72>(Fc, Bsg, mBaseS, nBaseS, g, tig, acc_s);
        // exp -> P (16-bit interleaved, stride 144 halves), accumulate sums
#pragma unroll
        for (int i = 0; i < 2; i++) {
            int row = mBaseS + i * 16 + g;
            int r2a = (row >> 1) * 144 + (row & 1);
            int r2b = r2a + 4 * 144;
#pragma unroll
            for (int j = 0; j < 2; j++) {
                int col = nBaseS + j * 8 + 2 * tig;
                float e0 = ex2f(acc_s[i][j][0]);
                float e1 = ex2f(acc_s[i][j][1]);
                float e2 = ex2f(acc_s[i][j][2]);
                float e3 = ex2f(acc_s[i][j][3]);
                esum[j][0] += e0 + e2;
                esum[j][1] += e1 + e3;
                P16[r2a + col * 2]       = __float2bfloat16_rn(e0);
                P16[r2a + (col + 1) * 2] = __float2bfloat16_rn(e1);
                P16[r2b + col * 2]       = __float2bfloat16_rn(e2);
                P16[r2b + (col + 1) * 2] = __float2bfloat16_rn(e3);
                acc_s[i][j][0] = 0.f; acc_s[i][j][1] = 0.f;
                acc_s[i][j][2] = 0.f; acc_s[i][j][3] = 0.f;
            }
        }
        __syncthreads();                         // P visible
        // GEMM2: o[c 128][m 64] += hh^T P, K=64
        mma_ktile<4, 2, 136, 72>(Hc,            P,           mBaseO, nBaseO, g, tig, acc_o);
        mma_ktile<4, 2, 136, 72>(Hc + 16 * 136, P + 16 * 72, mBaseO, nBaseO, g, tig, acc_o);
    }
#pragma unroll
    for (int j = 0; j < 2; j++) {
        int col = nBaseO + j * 8 + 2 * tig;
        atomicAdd(&rowsum[col],     esum[j][0]);
        atomicAdd(&rowsum[col + 1], esum[j][1]);
    }
    __syncthreads();
    // store o as packed bf16 pairs (row, row+8) -> g_op[b][k2][m]
#pragma unroll
    for (int j = 0; j < 2; j++) {
        int col = nBaseO + j * 8 + 2 * tig;
        float inv0 = 1.f / rowsum[col], inv1 = 1.f / rowsum[col + 1];
#pragma unroll
        for (int i = 0; i < 4; i++) {
            int k2 = (mBaseO >> 1) + i * 8 + g;
            uint2 o;
            o.x = packbf(acc_o[i][j][0] * inv0, acc_o[i][j][2] * inv0);
            o.y = packbf(acc_o[i][j][1] * inv1, acc_o[i][j][3] * inv1);
            *(uint2*)&g_op[((size_t)(b * 64 + k2) << 12) + m0 + col] = o;
        }
    }
}

// =====================================================================
// final: out = conv4'(o) + gbeta + x. BM=64, BN=128, cp.async double buffer.
// grid (32 p-tiles, 4 m-tiles, NB)
// =====================================================================
__global__ __launch_bounds__(256) void final_mma_kernel(const float* __restrict__ x,
                                                        float* __restrict__ out)
{
    __shared__ unsigned As2[2][16 * 72];
    __shared__ unsigned Bs2[2][16 * 136];
    const int b = blockIdx.z;
    const int m0 = blockIdx.y * 64, p0 = blockIdx.x * 128;
    const int t = threadIdx.x, lane = t & 31, w = t >> 5;
    const int g = lane >> 2, tig = lane & 3;
    const int mBase = (w >> 2) * 32, nBase = (w & 3) * 32;
    const int ar = t >> 4, as_ = t & 15;
    // prologue: stage kt=0
    cpa16(&As2[0][ar * 72 + as_ * 4], &g_w4p[ar * 256 + m0 + as_ * 4]);
#pragma unroll
    for (int p = 0; p < 2; p++) {
        int slot = t + p * 256, br = slot >> 5, bs = slot & 31;
        cpa16(&Bs2[0][br * 136 + bs * 4], &g_op[((size_t)(b * 64 + br) << 12) + p0 + bs * 4]);
    }
    cp_commit();
    float acc[2][4][4] = {};
    for (int kt = 0; kt < 4; kt++) {
        cp_wait<0>();
        __syncthreads();
        if (kt < 3) {
            const int bn = (kt + 1) & 1;
            cpa16(&As2[bn][ar * 72 + as_ * 4],
                  &g_w4p[((kt + 1) * 16 + ar) * 256 + m0 + as_ * 4]);
#pragma unroll
            for (int p = 0; p < 2; p++) {
                int slot = t + p * 256, br = slot >> 5, bs = slot & 31;
                cpa16(&Bs2[bn][br * 136 + bs * 4],
                      &g_op[((size_t)(b * 64 + (kt + 1) * 16 + br) << 12) + p0 + bs * 4]);
            }
            cp_commit();
        }
        mma_ktile<2, 4, 72, 136>(As2[kt & 1], Bs2[kt & 1], mBase, nBase, g, tig, acc);
    }
#pragma unroll
    for (int i = 0; i < 2; i++) {
#pragma unroll
        for (int half = 0; half < 2; half++) {
            int r = m0 + mBase + i * 16 + g + half * 8;
            float gb = g_ab4[256 + r];
            size_t base = ((size_t)(b * 256 + r) << 12) + p0;
#pragma unroll
            for (int j = 0; j < 4; j++) {
                int col = nBase + j * 8 + 2 * tig;
                float2 xv = *(const float2*)&x[base + col];
                float2 o;
                o.x = acc[i][j][half * 2 + 0] + gb + xv.x;
                o.y = acc[i][j][half * 2 + 1] + gb + xv.y;
                *(float2*)&out[base + col] = o;
            }
        }
    }
}

// =====================================================================
extern "C" void kernel_launch(void* const* d_in, const int* in_sizes, int n_in,
                              void* d_out, int out_size)
{
    const float* x  = (const float*)d_in[0];
    const float* w1 = (const float*)d_in[1],  *b1 = (const float*)d_in[2],
               * s1 = (const float*)d_in[3],  *t1 = (const float*)d_in[4],
               * m1 = (const float*)d_in[5],  *v1 = (const float*)d_in[6];
    const float* w2 = (const float*)d_in[7],  *b2 = (const float*)d_in[8],
               * s2 = (const float*)d_in[9],  *t2 = (const float*)d_in[10],
               * m2 = (const float*)d_in[11], *v2 = (const float*)d_in[12];
    const float* w3 = (const float*)d_in[13], *b3 = (const float*)d_in[14],
               * s3 = (const float*)d_in[15], *t3 = (const float*)d_in[16],
               * m3 = (const float*)d_in[17], *v3 = (const float*)d_in[18];
    const float* w4 = (const float*)d_in[19], *b4 = (const float*)d_in[20],
               * s4 = (const float*)d_in[21], *t4 = (const float*)d_in[22],
               * m4 = (const float*)d_in[23], *v4 = (const float*)d_in[24];
    const float* gamma = (const float*)d_in[25];
    float* out = (float*)d_out;

    cudaFuncSetAttribute(fused_attn_kernel,
                         cudaFuncAttributeMaxDynamicSharedMemorySize, 59392);

    pre_kernel<<<162, 256>>>(w1, w2, w3, w4,
                             b1, s1, t1, m1, v1,
                             b2, s2, t2, m2, v2,
                             b3, s3, t3, m3, v3,
                             b4, s4, t4, m4, v4, gamma);

    proj_pool_kernel<<<dim3(32, 3, NB), 256>>>(x);

    fused_attn_kernel<<<dim3(64, NB), 256, 58112>>>();

    final_mma_kernel<<<dim3(32, 4, NB), 256>>>(x, out);
}

// round 8
// speedup vs baseline: 6.2896x; 1.0673x over previous
#include <cuda_runtime.h>
#include <cuda_bf16.h>
#include <math.h>

#define NB 8
#define NC 256
#define HWF 4096
#define HW4 1024
#define EPSV 1e-5f
#define LOG2E 1.4426950408889634f

// ---------------- scratch (static __device__, word-typed, no allocation) ----
__device__ unsigned g_wpb [24576];               // proj wT bf16 [k=256][m=192], alpha-folded (m-pairs/word)
__device__ unsigned g_w4b [16384];               // w4T bf16 [k=128][m=256], gamma*alpha4 folded
__device__ float    g_abp[2 * 192];              // proj beta
__device__ float    g_ab4[2 * 256];              // final gamma*beta4 in [256..]
__device__ unsigned g_fb [NB * 32 * 512];        // f bf16 [b][k=32][n=1024]  (log2e folded)
__device__ unsigned g_gb [NB * 32 * 2048];       // g bf16 [b][k=32][m=4096]
__device__ unsigned g_hh2[NB * 1024 * 64];       // hh bf16 [b][n=1024][c=128]
__device__ unsigned g_ob [NB * 128 * 2048];      // o bf16 [b][c=128][m=4096]

// ---------------- helpers ----------------
__device__ __forceinline__ unsigned packbf(float a, float b) {
    __nv_bfloat162 t = __floats2bfloat162_rn(a, b);
    return *(unsigned*)&t;
}
__device__ __forceinline__ float ex2f(float f) {
    float r; asm("ex2.approx.ftz.f32 %0, %1;" : "=f"(r) : "f"(f)); return r;
}
__device__ __forceinline__ void cpa16(void* s, const void* g) {
    unsigned a = (unsigned)__cvta_generic_to_shared(s);
    asm volatile("cp.async.ca.shared.global [%0], [%1], 16;" :: "r"(a), "l"(g));
}
__device__ __forceinline__ void cp_commit() { asm volatile("cp.async.commit_group;"); }
template<int N> __device__ __forceinline__ void cp_wait() {
    asm volatile("cp.async.wait_group %0;" :: "n"(N));
}
__device__ __forceinline__ void ldsm4t(unsigned* r, const __nv_bfloat16* p) {
    unsigned a = (unsigned)__cvta_generic_to_shared(p);
    asm volatile("ldmatrix.sync.aligned.m8n8.x4.trans.shared.b16 {%0,%1,%2,%3}, [%4];"
                 : "=r"(r[0]), "=r"(r[1]), "=r"(r[2]), "=r"(r[3]) : "r"(a));
}
__device__ __forceinline__ void mma16(float* d, const unsigned* a, const unsigned* b) {
    asm volatile(
        "mma.sync.aligned.m16n8k16.row.col.f32.bf16.bf16.f32 "
        "{%0,%1,%2,%3},{%4,%5,%6,%7},{%8,%9},{%0,%1,%2,%3};"
        : "+f"(d[0]), "+f"(d[1]), "+f"(d[2]), "+f"(d[3])
        : "r"(a[0]), "r"(a[1]), "r"(a[2]), "r"(a[3]), "r"(b[0]), "r"(b[1]));
}

// A-frag (m16k16) from [k][row] smem, stride S halfwords, via ldmatrix.x4.trans
template<int S>
__device__ __forceinline__ void lda(unsigned* a, const __nv_bfloat16* base,
                                    int mo, int k0, int lane) {
    int grp = lane >> 3, j = lane & 7;
    int row = k0 + ((grp & 2) << 2) + j;
    int col = mo + ((grp & 1) << 3);
    ldsm4t(a, base + row * S + col);
}
// two B-frags (n8k16 at no, no+8) in one x4.trans: out b[0..1], b[2..3]
template<int S>
__device__ __forceinline__ void ldb2(unsigned* b, const __nv_bfloat16* base,
                                     int no, int k0, int lane) {
    int grp = lane >> 3, j = lane & 7;
    int row = k0 + ((grp & 1) << 3) + j;
    int col = no + ((grp >> 1) << 3);
    ldsm4t(b, base + row * S + col);
}

// one 32-deep k tile. As[k][m] stride AS, Bs[k][n] stride BS (halfwords).
template<int MF, int NF, int AS, int BS>
__device__ __forceinline__ void mma_ktile(const __nv_bfloat16* As, const __nv_bfloat16* Bs,
                                          int mBase, int nBase, int lane,
                                          float (*acc)[NF][4])
{
#pragma unroll
    for (int ks = 0; ks < 2; ks++) {
        unsigned a[MF][4], b[NF][2];
#pragma unroll
        for (int i = 0; i < MF; i++) lda<AS>(a[i], As, mBase + i * 16, ks * 16, lane);
#pragma unroll
        for (int j = 0; j < NF; j += 2) {
            unsigned bb[4];
            ldb2<BS>(bb, Bs, nBase + j * 8, ks * 16, lane);
            b[j][0] = bb[0]; b[j][1] = bb[1];
            b[j + 1][0] = bb[2]; b[j + 1][1] = bb[3];
        }
#pragma unroll
        for (int i = 0; i < MF; i++)
#pragma unroll
            for (int j = 0; j < NF; j++)
                mma16(acc[i][j], a[i], b[j]);
    }
}

// =====================================================================
// pre
// =====================================================================
__global__ void pre_kernel(const float* __restrict__ w1, const float* __restrict__ w2,
                           const float* __restrict__ w3, const float* __restrict__ w4,
                           const float* __restrict__ b1, const float* __restrict__ s1,
                           const float* __restrict__ t1, const float* __restrict__ m1,
                           const float* __restrict__ v1,
                           const float* __restrict__ b2, const float* __restrict__ s2,
                           const float* __restrict__ t2, const float* __restrict__ m2,
                           const float* __restrict__ v2,
                           const float* __restrict__ b3, const float* __restrict__ s3,
                           const float* __restrict__ t3, const float* __restrict__ m3,
                           const float* __restrict__ v3,
                           const float* __restrict__ b4, const float* __restrict__ s4,
                           const float* __restrict__ t4, const float* __restrict__ m4,
                           const float* __restrict__ v4,
                           const float* __restrict__ gamma)
{
    int idx = blockIdx.x * 256 + threadIdx.x;
    if (idx < 24576) {                       // wpb [k][m] m-pairs
        int k = idx / 96, mw = idx % 96, m = 2 * mw;
        float a0, a1, v0, v1_;
        if (m < 32)      { a0 = s1[m] * rsqrtf(v1[m] + EPSV) * LOG2E;
                           a1 = s1[m + 1] * rsqrtf(v1[m + 1] + EPSV) * LOG2E;
                           v0 = w1[m * 256 + k]; v1_ = w1[(m + 1) * 256 + k]; }
        else if (m < 64) { a0 = s2[m - 32] * rsqrtf(v2[m - 32] + EPSV);
                           a1 = s2[m - 31] * rsqrtf(v2[m - 31] + EPSV);
                           v0 = w2[(m - 32) * 256 + k]; v1_ = w2[(m - 31) * 256 + k]; }
        else             { a0 = s3[m - 64] * rsqrtf(v3[m - 64] + EPSV);
                           a1 = s3[m - 63] * rsqrtf(v3[m - 63] + EPSV);
                           v0 = w3[(m - 64) * 256 + k]; v1_ = w3[(m - 63) * 256 + k]; }
        g_wpb[idx] = packbf(v0 * a0, v1_ * a1);
        return;
    }
    idx -= 24576;
    if (idx < 16384) {                       // w4b [k][m] m-pairs
        int k = idx / 128, mw = idx % 128, m = 2 * mw;
        float a0 = s4[m] * rsqrtf(v4[m] + EPSV) * gamma[0];
        float a1 = s4[m + 1] * rsqrtf(v4[m + 1] + EPSV) * gamma[0];
        g_w4b[idx] = packbf(w4[m * 128 + k] * a0, w4[(m + 1) * 128 + k] * a1);
        return;
    }
    idx -= 16384;
    if (idx < 192) {
        int r = idx;
        float bb, ss, tt, mm, vv, lg = 1.f;
        if (r < 32)      { bb = b1[r];      ss = s1[r];      tt = t1[r];      mm = m1[r];      vv = v1[r]; lg = LOG2E; }
        else if (r < 64) { bb = b2[r - 32]; ss = s2[r - 32]; tt = t2[r - 32]; mm = m2[r - 32]; vv = v2[r - 32]; }
        else             { bb = b3[r - 64]; ss = s3[r - 64]; tt = t3[r - 64]; mm = m3[r - 64]; vv = v3[r - 64]; }
        float alpha = ss * rsqrtf(vv + EPSV);
        g_abp[192 + r] = fmaf(bb - mm, alpha, tt) * lg;
        return;
    }
    idx -= 192;
    if (idx < 256) {
        int r = idx;
        float alpha = s4[r] * rsqrtf(v4[r] + EPSV);
        g_ab4[256 + r] = fmaf(b4[r] - m4[r], alpha, t4[r]) * gamma[0];
    }
}

// =====================================================================
// proj+pool: GEMM(M=64 slice, K=256, N=128) + BN + ReLU, pool + route.
// smem operands: As[k=32][m=64+8], Bs[k=32][p=128+8] bf16; T fp32 union.
// grid (32 p-tiles, 3 m-slices, NB)
// =====================================================================
__global__ __launch_bounds__(256) void proj_pool_kernel(const float* __restrict__ x)
{
    __shared__ __align__(16) union {
        struct { __nv_bfloat16 As[32 * 72]; __nv_bfloat16 Bs[32 * 136]; } s;
        float T[64 * 132];
    } u;
    const int b = blockIdx.z;
    const int my = blockIdx.y, m0 = my * 64;
    const int bx = blockIdx.x, p0 = bx * 128;
    const int t = threadIdx.x, lane = t & 31, w = t >> 5;
    const int g = lane >> 2, tig = lane & 3;
    const int mBase = (w >> 2) * 32, nBase = (w & 3) * 32;
    const float* xb = x + ((size_t)b << 20);
    const int ar = t >> 3, aseg = (t & 7) * 8;       // A: 32 rows x 8 chunks(hw)
    float acc[2][4][4] = {};
    // prefetch kt=0
    uint4 wA = *(const uint4*)&g_wpb[(ar * 192 + m0 + aseg) >> 1];
    float4 va[4];
#pragma unroll
    for (int p = 0; p < 4; p++) {
        int slot = t + p * 256, r = slot >> 5, c4 = (slot & 31) * 4;
        va[p] = *(const float4*)&xb[((size_t)r << 12) + p0 + c4];
    }
    for (int kt = 0; kt < 8; kt++) {
        *(uint4*)&u.s.As[ar * 72 + aseg] = wA;
#pragma unroll
        for (int p = 0; p < 4; p++) {
            int slot = t + p * 256, r = slot >> 5, c4 = (slot & 31) * 4;
            unsigned* d = (unsigned*)&u.s.Bs[r * 136 + c4];
            d[0] = packbf(va[p].x, va[p].y);
            d[1] = packbf(va[p].z, va[p].w);
        }
        __syncthreads();
        if (kt < 7) {
            const int k0 = (kt + 1) * 32;
            wA = *(const uint4*)&g_wpb[(((kt + 1) * 32 + ar) * 192 + m0 + aseg) >> 1];
#pragma unroll
            for (int p = 0; p < 4; p++) {
                int slot = t + p * 256, r = slot >> 5, c4 = (slot & 31) * 4;
                va[p] = *(const float4*)&xb[((size_t)(k0 + r) << 12) + p0 + c4];
            }
        }
        mma_ktile<2, 4, 72, 136>(u.s.As, u.s.Bs, mBase, nBase, lane, acc);
        __syncthreads();
    }
    // BN + ReLU into T[m 64][p 128] (stride 132)
#pragma unroll
    for (int i = 0; i < 2; i++) {
#pragma unroll
        for (int half = 0; half < 2; half++) {
            int rl = mBase + i * 16 + g + half * 8;
            float beta = g_abp[192 + m0 + rl];
#pragma unroll
            for (int j = 0; j < 4; j++) {
                int col = nBase + j * 8 + 2 * tig;
                u.T[rl * 132 + col]     = fmaxf(acc[i][j][half * 2 + 0] + beta, 0.f);
                u.T[rl * 132 + col + 1] = fmaxf(acc[i][j][half * 2 + 1] + beta, 0.f);
            }
        }
    }
    __syncthreads();
    if (my == 0) {
        // f: rows 0-31 pooled -> g_fb[b][k][n] (4 n per thread)
        {
            int k = t >> 3, nq = (t & 7) * 4;
            const float* r0 = &u.T[k * 132 + 2 * nq];
            unsigned w0 = packbf(fmaxf(fmaxf(r0[0], r0[1]), fmaxf(r0[64], r0[65])),
                                 fmaxf(fmaxf(r0[2], r0[3]), fmaxf(r0[66], r0[67])));
            unsigned w1_ = packbf(fmaxf(fmaxf(r0[4], r0[5]), fmaxf(r0[68], r0[69])),
                                  fmaxf(fmaxf(r0[6], r0[7]), fmaxf(r0[70], r0[71])));
            *(uint2*)&g_fb[((b * 32 + k) * 1024 + bx * 32 + nq) >> 1] = make_uint2(w0, w1_);
        }
        // g: rows 32-63 copy -> g_gb[b][k][m] (16 m per thread)
        {
            int k = t >> 3, mq = (t & 7) * 16;
            const float* r0 = &u.T[(32 + k) * 132 + mq];
            uint4 o0, o1;
            o0.x = packbf(r0[0],  r0[1]);  o0.y = packbf(r0[2],  r0[3]);
            o0.z = packbf(r0[4],  r0[5]);  o0.w = packbf(r0[6],  r0[7]);
            o1.x = packbf(r0[8],  r0[9]);  o1.y = packbf(r0[10], r0[11]);
            o1.z = packbf(r0[12], r0[13]); o1.w = packbf(r0[14], r0[15]);
            unsigned base = ((b * 32 + k) * 4096 + p0 + mq) >> 1;
            *(uint4*)&g_gb[base] = o0;
            *(uint4*)&g_gb[base + 4] = o1;
        }
    } else {
        // hh: 64 channels pooled -> g_hh2[b][n][c] (8 c per thread at one n)
        const int cg0 = (my - 1) * 64;
        int n = t & 31, cq = (t >> 5) * 8;
        unsigned pk[4];
#pragma unroll
        for (int cc = 0; cc < 4; cc++) {
            const float* ra = &u.T[(cq + 2 * cc) * 132 + 2 * n];
            const float* rb = &u.T[(cq + 2 * cc + 1) * 132 + 2 * n];
            float v0 = fmaxf(fmaxf(ra[0], ra[1]), fmaxf(ra[64], ra[65]));
            float v1_ = fmaxf(fmaxf(rb[0], rb[1]), fmaxf(rb[64], rb[65]));
            pk[cc] = packbf(v0, v1_);
        }
        *(uint4*)&g_hh2[((b * 1024 + bx * 32 + n) * 128 + cg0 + cq) >> 1] =
            make_uint4(pk[0], pk[1], pk[2], pk[3]);
    }
}

// =====================================================================
// fused attention, BM(m)=64/CTA, cp.async double-buffered f/hh.
// smem (halfwords): Bsg[32x72] | F[2][32x72] | H[2][64x136] | P[64x72] | rowsum
// =====================================================================
__global__ __launch_bounds__(256, 2) void fused_attn_kernel()
{
    extern __shared__ __align__(16) char dsm[];
    __nv_bfloat16* Bsg = (__nv_bfloat16*)dsm;                 // 32x72
    __nv_bfloat16* F   = (__nv_bfloat16*)(dsm + 4608);        // 2 x 32x72
    __nv_bfloat16* H   = (__nv_bfloat16*)(dsm + 13824);       // 2 x 64x136
    __nv_bfloat16* P   = (__nv_bfloat16*)(dsm + 48640);       // 64x72
    float* rowsum      = (float*)(dsm + 57856);               // 64
    const int b = blockIdx.y, m0 = blockIdx.x * 64;
    const int t = threadIdx.x, lane = t & 31, w = t >> 5;
    const int g = lane >> 2, tig = lane & 3;
    const int mBaseS = (w >> 2) * 32, nBaseS = (w & 3) * 16;   // GEMM1: n x m
    const int mBaseO = (w >> 2) * 64, nBaseO = (w & 3) * 16;   // GEMM2: c x m
    if (t < 64) rowsum[t] = 0.f;

    const __nv_bfloat16* fb  = (const __nv_bfloat16*)g_fb  + (size_t)b * 32 * 1024;
    const __nv_bfloat16* gbp = (const __nv_bfloat16*)g_gb  + (size_t)b * 32 * 4096;
    const __nv_bfloat16* hhb = (const __nv_bfloat16*)g_hh2 + (size_t)b * 1024 * 128;

    const int fr = t >> 3, fseg = (t & 7) * 8;                 // 32 rows x 8 chunks
    // prologue: Bsg + stage 0
    cpa16(&Bsg[fr * 72 + fseg], &gbp[fr * 4096 + m0 + fseg]);
    cpa16(&F[fr * 72 + fseg], &fb[fr * 1024 + fseg]);
#pragma unroll
    for (int p = 0; p < 4; p++) {
        int slot = t + p * 256, hr = slot >> 4, hseg = (slot & 15) * 8;
        cpa16(&H[hr * 136 + hseg], &hhb[hr * 128 + hseg]);
    }
    cp_commit();

    float acc_s[2][2][4] = {};
    float acc_o[4][2][4] = {};
    float esum[2][2] = {};

    for (int nt = 0; nt < 16; nt++) {
        cp_wait<0>();
        __syncthreads();                         // F/H[cur] ready; GEMM2(nt-1) done
        if (nt < 15) {
            const int bn = (nt + 1) & 1;
            cpa16(&F[bn * 2304 + fr * 72 + fseg], &fb[fr * 1024 + (nt + 1) * 64 + fseg]);
#pragma unroll
            for (int p = 0; p < 4; p++) {
                int slot = t + p * 256, hr = slot >> 4, hseg = (slot & 15) * 8;
                cpa16(&H[bn * 8704 + hr * 136 + hseg],
                      &hhb[(size_t)((nt + 1) * 64 + hr) * 128 + hseg]);
            }
            cp_commit();
        }
        const __nv_bfloat16* Fc = F + (nt & 1) * 2304;
        const __nv_bfloat16* Hc = H + (nt & 1) * 8704;
        // GEMM1: s[n 64][m 64], K=32
        mma_ktile<2, 2, 72, 72>(Fc, Bsg, mBaseS, nBaseS, lane, acc_s);
        // exp -> P[n][m], accumulate column sums
#pragma unroll
        for (int i = 0; i < 2; i++) {
            int row = mBaseS + i * 16 + g;
#pragma unroll
            for (int j = 0; j < 2; j++) {
                int col = nBaseS + j * 8 + 2 * tig;
                float e0 = ex2f(acc_s[i][j][0]);
                float e1 = ex2f(acc_s[i][j][1]);
                float e2 = ex2f(acc_s[i][j][2]);
                float e3 = ex2f(acc_s[i][j][3]);
                esum[j][0] += e0 + e2;
                esum[j][1] += e1 + e3;
                *(unsigned*)&P[row * 72 + col]       = packbf(e0, e1);
                *(unsigned*)&P[(row + 8) * 72 + col] = packbf(e2, e3);
                acc_s[i][j][0] = 0.f; acc_s[i][j][1] = 0.f;
                acc_s[i][j][2] = 0.f; acc_s[i][j][3] = 0.f;
            }
        }
        __syncthreads();                         // P visible
        // GEMM2: o[c 128][m 64] += hh^T P, K=64
        mma_ktile<4, 2, 136, 72>(Hc,            P,           mBaseO, nBaseO, lane, acc_o);
        mma_ktile<4, 2, 136, 72>(Hc + 32 * 136, P + 32 * 72, mBaseO, nBaseO, lane, acc_o);
    }
#pragma unroll
    for (int j = 0; j < 2; j++) {
        int col = nBaseO + j * 8 + 2 * tig;
        atomicAdd(&rowsum[col],     esum[j][0]);
        atomicAdd(&rowsum[col + 1], esum[j][1]);
    }
    __syncthreads();
    // store o bf16 [b][c][m]
#pragma unroll
    for (int j = 0; j < 2; j++) {
        int col = nBaseO + j * 8 + 2 * tig;
        float inv0 = 1.f / rowsum[col], inv1 = 1.f / rowsum[col + 1];
#pragma unroll
        for (int i = 0; i < 4; i++) {
            int c = mBaseO + i * 16 + g;
            g_ob[((b * 128 + c) * 4096 + m0 + col) >> 1] =
                packbf(acc_o[i][j][0] * inv0, acc_o[i][j][1] * inv1);
            g_ob[((b * 128 + c + 8) * 4096 + m0 + col) >> 1] =
                packbf(acc_o[i][j][2] * inv0, acc_o[i][j][3] * inv1);
        }
    }
}

// =====================================================================
// final: out = conv4'(o) + gbeta + x. BM=64, BN=128, cp.async double buffer.
// grid (32 p-tiles, 4 m-tiles, NB)
// =====================================================================
__global__ __launch_bounds__(256) void final_mma_kernel(const float* __restrict__ x,
                                                        float* __restrict__ out)
{
    __shared__ __align__(16) __nv_bfloat16 As2[2][32 * 72];
    __shared__ __align__(16) __nv_bfloat16 Bs2[2][32 * 136];
    const int b = blockIdx.z;
    const int m0 = blockIdx.y * 64, p0 = blockIdx.x * 128;
    const int t = threadIdx.x, lane = t & 31, w = t >> 5;
    const int g = lane >> 2, tig = lane & 3;
    const int mBase = (w >> 2) * 32, nBase = (w & 3) * 32;
    const __nv_bfloat16* w4b = (const __nv_bfloat16*)g_w4b;
    const __nv_bfloat16* ob  = (const __nv_bfloat16*)g_ob + (size_t)b * 128 * 4096;
    const int ar = t >> 3, aseg = (t & 7) * 8;
    // prologue kt=0
    cpa16(&As2[0][ar * 72 + aseg], &w4b[ar * 256 + m0 + aseg]);
#pragma unroll
    for (int p = 0; p < 2; p++) {
        int slot = t + p * 256, br = slot >> 4, bseg = (slot & 15) * 8;
        cpa16(&Bs2[0][br * 136 + bseg], &ob[(size_t)br * 4096 + p0 + bseg]);
    }
    cp_commit();
    float acc[2][4][4] = {};
    for (int kt = 0; kt < 4; kt++) {
        cp_wait<0>();
        __syncthreads();
        if (kt < 3) {
            const int bn = (kt + 1) & 1;
            cpa16(&As2[bn][ar * 72 + aseg],
                  &w4b[((kt + 1) * 32 + ar) * 256 + m0 + aseg]);
#pragma unroll
            for (int p = 0; p < 2; p++) {
                int slot = t + p * 256, br = slot >> 4, bseg = (slot & 15) * 8;
                cpa16(&Bs2[bn][br * 136 + bseg],
                      &ob[(size_t)((kt + 1) * 32 + br) * 4096 + p0 + bseg]);
            }
            cp_commit();
        }
        mma_ktile<2, 4, 72, 136>(As2[kt & 1], Bs2[kt & 1], mBase, nBase, lane, acc);
    }
#pragma unroll
    for (int i = 0; i < 2; i++) {
#pragma unroll
        for (int half = 0; half < 2; half++) {
            int r = m0 + mBase + i * 16 + g + half * 8;
            float gb = g_ab4[256 + r];
            size_t base = ((size_t)(b * 256 + r) << 12) + p0;
#pragma unroll
            for (int j = 0; j < 4; j++) {
                int col = nBase + j * 8 + 2 * tig;
                float2 xv = *(const float2*)&x[base + col];
                float2 o;
                o.x = acc[i][j][half * 2 + 0] + gb + xv.x;
                o.y = acc[i][j][half * 2 + 1] + gb + xv.y;
                *(float2*)&out[base + col] = o;
            }
        }
    }
}

// =====================================================================
extern "C" void kernel_launch(void* const* d_in, const int* in_sizes, int n_in,
                              void* d_out, int out_size)
{
    const float* x  = (const float*)d_in[0];
    const float* w1 = (const float*)d_in[1],  *b1 = (const float*)d_in[2],
               * s1 = (const float*)d_in[3],  *t1 = (const float*)d_in[4],
               * m1 = (const float*)d_in[5],  *v1 = (const float*)d_in[6];
    const float* w2 = (const float*)d_in[7],  *b2 = (const float*)d_in[8],
               * s2 = (const float*)d_in[9],  *t2 = (const float*)d_in[10],
               * m2 = (const float*)d_in[11], *v2 = (const float*)d_in[12];
    const float* w3 = (const float*)d_in[13], *b3 = (const float*)d_in[14],
               * s3 = (const float*)d_in[15], *t3 = (const float*)d_in[16],
               * m3 = (const float*)d_in[17], *v3 = (const float*)d_in[18];
    const float* w4 = (const float*)d_in[19], *b4 = (const float*)d_in[20],
               * s4 = (const float*)d_in[21], *t4 = (const float*)d_in[22],
               * m4 = (const float*)d_in[23], *v4 = (const float*)d_in[24];
    const float* gamma = (const float*)d_in[25];
    float* out = (float*)d_out;

    cudaFuncSetAttribute(fused_attn_kernel,
                         cudaFuncAttributeMaxDynamicSharedMemorySize, 59392);

    pre_kernel<<<162, 256>>>(w1, w2, w3, w4,
                             b1, s1, t1, m1, v1,
                             b2, s2, t2, m2, v2,
                             b3, s3, t3, m3, v3,
                             b4, s4, t4, m4, v4, gamma);

    proj_pool_kernel<<<dim3(32, 3, NB), 256>>>(x);

    fused_attn_kernel<<<dim3(64, NB), 256, 58112>>>();

    final_mma_kernel<<<dim3(32, 4, NB), 256>>>(x, out);
}

// round 9
// speedup vs baseline: 6.5206x; 1.0367x over previous
#include <cuda_runtime.h>
#include <cuda_bf16.h>
#include <math.h>

#define NB 8
#define NC 256
#define HWF 4096
#define HW4 1024
#define EPSV 1e-5f
#define LOG2E 1.4426950408889634f

// ---------------- scratch (static __device__, word-typed, no allocation) ----
__device__ unsigned g_wpb [24576];               // proj wT bf16 [k=256][m=192], alpha-folded (m-pairs/word)
__device__ unsigned g_w4b [16384];               // w4T bf16 [k=128][m=256], gamma*alpha4 folded
__device__ float    g_abp[2 * 192];              // proj beta
__device__ float    g_ab4[2 * 256];              // final gamma*beta4 in [256..]
__device__ unsigned g_fb [NB * 32 * 512];        // f bf16 [b][k=32][n=1024]  (log2e folded)
__device__ unsigned g_gb [NB * 32 * 2048];       // g bf16 [b][k=32][m=4096]
__device__ unsigned g_hh2[NB * 1024 * 64];       // hh bf16 [b][n=1024][c=128]

// ---------------- helpers ----------------
__device__ __forceinline__ unsigned packbf(float a, float b) {
    __nv_bfloat162 t = __floats2bfloat162_rn(a, b);
    return *(unsigned*)&t;
}
__device__ __forceinline__ float ex2f(float f) {
    float r; asm("ex2.approx.ftz.f32 %0, %1;" : "=f"(r) : "f"(f)); return r;
}
__device__ __forceinline__ void cpa16(void* s, const void* g) {
    unsigned a = (unsigned)__cvta_generic_to_shared(s);
    asm volatile("cp.async.ca.shared.global [%0], [%1], 16;" :: "r"(a), "l"(g));
}
__device__ __forceinline__ void cp_commit() { asm volatile("cp.async.commit_group;"); }
template<int N> __device__ __forceinline__ void cp_wait() {
    asm volatile("cp.async.wait_group %0;" :: "n"(N));
}
__device__ __forceinline__ void ldsm4t(unsigned* r, const __nv_bfloat16* p) {
    unsigned a = (unsigned)__cvta_generic_to_shared(p);
    asm volatile("ldmatrix.sync.aligned.m8n8.x4.trans.shared.b16 {%0,%1,%2,%3}, [%4];"
                 : "=r"(r[0]), "=r"(r[1]), "=r"(r[2]), "=r"(r[3]) : "r"(a));
}
__device__ __forceinline__ void mma16(float* d, const unsigned* a, const unsigned* b) {
    asm volatile(
        "mma.sync.aligned.m16n8k16.row.col.f32.bf16.bf16.f32 "
        "{%0,%1,%2,%3},{%4,%5,%6,%7},{%8,%9},{%0,%1,%2,%3};"
        : "+f"(d[0]), "+f"(d[1]), "+f"(d[2]), "+f"(d[3])
        : "r"(a[0]), "r"(a[1]), "r"(a[2]), "r"(a[3]), "r"(b[0]), "r"(b[1]));
}

// A-frag (m16k16) from [k][row] smem, stride S halfwords, via ldmatrix.x4.trans
template<int S>
__device__ __forceinline__ void lda(unsigned* a, const __nv_bfloat16* base,
                                    int mo, int k0, int lane) {
    int grp = lane >> 3, j = lane & 7;
    int row = k0 + ((grp & 2) << 2) + j;
    int col = mo + ((grp & 1) << 3);
    ldsm4t(a, base + row * S + col);
}
// two B-frags (n8k16 at no, no+8) in one x4.trans: out b[0..1], b[2..3]
template<int S>
__device__ __forceinline__ void ldb2(unsigned* b, const __nv_bfloat16* base,
                                     int no, int k0, int lane) {
    int grp = lane >> 3, j = lane & 7;
    int row = k0 + ((grp & 1) << 3) + j;
    int col = no + ((grp >> 1) << 3);
    ldsm4t(b, base + row * S + col);
}

// one 32-deep k tile. As[k][m] stride AS, Bs[k][n] stride BS (halfwords).
template<int MF, int NF, int AS, int BS>
__device__ __forceinline__ void mma_ktile(const __nv_bfloat16* As, const __nv_bfloat16* Bs,
                                          int mBase, int nBase, int lane,
                                          float (*acc)[NF][4])
{
#pragma unroll
    for (int ks = 0; ks < 2; ks++) {
        unsigned a[MF][4], b[NF][2];
#pragma unroll
        for (int i = 0; i < MF; i++) lda<AS>(a[i], As, mBase + i * 16, ks * 16, lane);
#pragma unroll
        for (int j = 0; j < NF; j += 2) {
            unsigned bb[4];
            ldb2<BS>(bb, Bs, nBase + j * 8, ks * 16, lane);
            b[j][0] = bb[0]; b[j][1] = bb[1];
            b[j + 1][0] = bb[2]; b[j + 1][1] = bb[3];
        }
#pragma unroll
        for (int i = 0; i < MF; i++)
#pragma unroll
            for (int j = 0; j < NF; j++)
                mma16(acc[i][j], a[i], b[j]);
    }
}

// =====================================================================
// pre
// =====================================================================
__global__ void pre_kernel(const float* __restrict__ w1, const float* __restrict__ w2,
                           const float* __restrict__ w3, const float* __restrict__ w4,
                           const float* __restrict__ b1, const float* __restrict__ s1,
                           const float* __restrict__ t1, const float* __restrict__ m1,
                           const float* __restrict__ v1,
                           const float* __restrict__ b2, const float* __restrict__ s2,
                           const float* __restrict__ t2, const float* __restrict__ m2,
                           const float* __restrict__ v2,
                           const float* __restrict__ b3, const float* __restrict__ s3,
                           const float* __restrict__ t3, const float* __restrict__ m3,
                           const float* __restrict__ v3,
                           const float* __restrict__ b4, const float* __restrict__ s4,
                           const float* __restrict__ t4, const float* __restrict__ m4,
                           const float* __restrict__ v4,
                           const float* __restrict__ gamma)
{
    int idx = blockIdx.x * 256 + threadIdx.x;
    if (idx < 24576) {                       // wpb [k][m] m-pairs
        int k = idx / 96, mw = idx % 96, m = 2 * mw;
        float a0, a1, v0, v1_;
        if (m < 32)      { a0 = s1[m] * rsqrtf(v1[m] + EPSV) * LOG2E;
                           a1 = s1[m + 1] * rsqrtf(v1[m + 1] + EPSV) * LOG2E;
                           v0 = w1[m * 256 + k]; v1_ = w1[(m + 1) * 256 + k]; }
        else if (m < 64) { a0 = s2[m - 32] * rsqrtf(v2[m - 32] + EPSV);
                           a1 = s2[m - 31] * rsqrtf(v2[m - 31] + EPSV);
                           v0 = w2[(m - 32) * 256 + k]; v1_ = w2[(m - 31) * 256 + k]; }
        else             { a0 = s3[m - 64] * rsqrtf(v3[m - 64] + EPSV);
                           a1 = s3[m - 63] * rsqrtf(v3[m - 63] + EPSV);
                           v0 = w3[(m - 64) * 256 + k]; v1_ = w3[(m - 63) * 256 + k]; }
        g_wpb[idx] = packbf(v0 * a0, v1_ * a1);
        return;
    }
    idx -= 24576;
    if (idx < 16384) {                       // w4b [k][m] m-pairs
        int k = idx / 128, mw = idx % 128, m = 2 * mw;
        float a0 = s4[m] * rsqrtf(v4[m] + EPSV) * gamma[0];
        float a1 = s4[m + 1] * rsqrtf(v4[m + 1] + EPSV) * gamma[0];
        g_w4b[idx] = packbf(w4[m * 128 + k] * a0, w4[(m + 1) * 128 + k] * a1);
        return;
    }
    idx -= 16384;
    if (idx < 192) {
        int r = idx;
        float bb, ss, tt, mm, vv, lg = 1.f;
        if (r < 32)      { bb = b1[r];      ss = s1[r];      tt = t1[r];      mm = m1[r];      vv = v1[r]; lg = LOG2E; }
        else if (r < 64) { bb = b2[r - 32]; ss = s2[r - 32]; tt = t2[r - 32]; mm = m2[r - 32]; vv = v2[r - 32]; }
        else             { bb = b3[r - 64]; ss = s3[r - 64]; tt = t3[r - 64]; mm = m3[r - 64]; vv = v3[r - 64]; }
        float alpha = ss * rsqrtf(vv + EPSV);
        g_abp[192 + r] = fmaf(bb - mm, alpha, tt) * lg;
        return;
    }
    idx -= 192;
    if (idx < 256) {
        int r = idx;
        float alpha = s4[r] * rsqrtf(v4[r] + EPSV);
        g_ab4[256 + r] = fmaf(b4[r] - m4[r], alpha, t4[r]) * gamma[0];
    }
}

// =====================================================================
// proj+pool (unchanged from R8)
// =====================================================================
__global__ __launch_bounds__(256) void proj_pool_kernel(const float* __restrict__ x)
{
    __shared__ __align__(16) union {
        struct { __nv_bfloat16 As[32 * 72]; __nv_bfloat16 Bs[32 * 136]; } s;
        float T[64 * 132];
    } u;
    const int b = blockIdx.z;
    const int my = blockIdx.y, m0 = my * 64;
    const int bx = blockIdx.x, p0 = bx * 128;
    const int t = threadIdx.x, lane = t & 31, w = t >> 5;
    const int g = lane >> 2, tig = lane & 3;
    const int mBase = (w >> 2) * 32, nBase = (w & 3) * 32;
    const float* xb = x + ((size_t)b << 20);
    const int ar = t >> 3, aseg = (t & 7) * 8;
    float acc[2][4][4] = {};
    uint4 wA = *(const uint4*)&g_wpb[(ar * 192 + m0 + aseg) >> 1];
    float4 va[4];
#pragma unroll
    for (int p = 0; p < 4; p++) {
        int slot = t + p * 256, r = slot >> 5, c4 = (slot & 31) * 4;
        va[p] = *(const float4*)&xb[((size_t)r << 12) + p0 + c4];
    }
    for (int kt = 0; kt < 8; kt++) {
        *(uint4*)&u.s.As[ar * 72 + aseg] = wA;
#pragma unroll
        for (int p = 0; p < 4; p++) {
            int slot = t + p * 256, r = slot >> 5, c4 = (slot & 31) * 4;
            unsigned* d = (unsigned*)&u.s.Bs[r * 136 + c4];
            d[0] = packbf(va[p].x, va[p].y);
            d[1] = packbf(va[p].z, va[p].w);
        }
        __syncthreads();
        if (kt < 7) {
            const int k0 = (kt + 1) * 32;
            wA = *(const uint4*)&g_wpb[(((kt + 1) * 32 + ar) * 192 + m0 + aseg) >> 1];
#pragma unroll
            for (int p = 0; p < 4; p++) {
                int slot = t + p * 256, r = slot >> 5, c4 = (slot & 31) * 4;
                va[p] = *(const float4*)&xb[((size_t)(k0 + r) << 12) + p0 + c4];
            }
        }
        mma_ktile<2, 4, 72, 136>(u.s.As, u.s.Bs, mBase, nBase, lane, acc);
        __syncthreads();
    }
#pragma unroll
    for (int i = 0; i < 2; i++) {
#pragma unroll
        for (int half = 0; half < 2; half++) {
            int rl = mBase + i * 16 + g + half * 8;
            float beta = g_abp[192 + m0 + rl];
#pragma unroll
            for (int j = 0; j < 4; j++) {
                int col = nBase + j * 8 + 2 * tig;
                u.T[rl * 132 + col]     = fmaxf(acc[i][j][half * 2 + 0] + beta, 0.f);
                u.T[rl * 132 + col + 1] = fmaxf(acc[i][j][half * 2 + 1] + beta, 0.f);
            }
        }
    }
    __syncthreads();
    if (my == 0) {
        {
            int k = t >> 3, nq = (t & 7) * 4;
            const float* r0 = &u.T[k * 132 + 2 * nq];
            unsigned w0 = packbf(fmaxf(fmaxf(r0[0], r0[1]), fmaxf(r0[64], r0[65])),
                                 fmaxf(fmaxf(r0[2], r0[3]), fmaxf(r0[66], r0[67])));
            unsigned w1_ = packbf(fmaxf(fmaxf(r0[4], r0[5]), fmaxf(r0[68], r0[69])),
                                  fmaxf(fmaxf(r0[6], r0[7]), fmaxf(r0[70], r0[71])));
            *(uint2*)&g_fb[((b * 32 + k) * 1024 + bx * 32 + nq) >> 1] = make_uint2(w0, w1_);
        }
        {
            int k = t >> 3, mq = (t & 7) * 16;
            const float* r0 = &u.T[(32 + k) * 132 + mq];
            uint4 o0, o1;
            o0.x = packbf(r0[0],  r0[1]);  o0.y = packbf(r0[2],  r0[3]);
            o0.z = packbf(r0[4],  r0[5]);  o0.w = packbf(r0[6],  r0[7]);
            o1.x = packbf(r0[8],  r0[9]);  o1.y = packbf(r0[10], r0[11]);
            o1.z = packbf(r0[12], r0[13]); o1.w = packbf(r0[14], r0[15]);
            unsigned base = ((b * 32 + k) * 4096 + p0 + mq) >> 1;
            *(uint4*)&g_gb[base] = o0;
            *(uint4*)&g_gb[base + 4] = o1;
        }
    } else {
        const int cg0 = (my - 1) * 64;
        int n = t & 31, cq = (t >> 5) * 8;
        unsigned pk[4];
#pragma unroll
        for (int cc = 0; cc < 4; cc++) {
            const float* ra = &u.T[(cq + 2 * cc) * 132 + 2 * n];
            const float* rb = &u.T[(cq + 2 * cc + 1) * 132 + 2 * n];
            float v0 = fmaxf(fmaxf(ra[0], ra[1]), fmaxf(ra[64], ra[65]));
            float v1_ = fmaxf(fmaxf(rb[0], rb[1]), fmaxf(rb[64], rb[65]));
            pk[cc] = packbf(v0, v1_);
        }
        *(uint4*)&g_hh2[((b * 1024 + bx * 32 + n) * 128 + cg0 + cq) >> 1] =
            make_uint4(pk[0], pk[1], pk[2], pk[3]);
    }
}

// =====================================================================
// fused attention + final conv, BM(m)=64/CTA.
// mainloop smem: Bsg[32x72] | F[2][32x72] | H[2][64x136] | P[64x72] | rowsum
// epilogue reuse: Po[128x72] at dsm | Wst[2][32x136] at dsm+20480
// out[oc 256][m 64] = w4^T (o/rowsum) + gbeta4 + x
// =====================================================================
__global__ __launch_bounds__(256, 2) void fused_attn_kernel(const float* __restrict__ x,
                                                            float* __restrict__ out)
{
    extern __shared__ __align__(16) char dsm[];
    __nv_bfloat16* Bsg = (__nv_bfloat16*)dsm;                 // 32x72
    __nv_bfloat16* F   = (__nv_bfloat16*)(dsm + 4608);        // 2 x 32x72
    __nv_bfloat16* H   = (__nv_bfloat16*)(dsm + 13824);       // 2 x 64x136
    __nv_bfloat16* P   = (__nv_bfloat16*)(dsm + 48640);       // 64x72
    float* rowsum      = (float*)(dsm + 57856);               // 64
    __nv_bfloat16* Po  = (__nv_bfloat16*)dsm;                 // 128x72 (epilogue)
    __nv_bfloat16* Wst = (__nv_bfloat16*)(dsm + 20480);       // 2 x 32x136 (epilogue)
    const int b = blockIdx.y, m0 = blockIdx.x * 64;
    const int t = threadIdx.x, lane = t & 31, w = t >> 5;
    const int g = lane >> 2, tig = lane & 3;
    const int mBaseS = (w >> 2) * 32, nBaseS = (w & 3) * 16;   // GEMM1: n x m
    const int mBaseO = (w >> 2) * 64, nBaseO = (w & 3) * 16;   // GEMM2/3: row x m
    if (t < 64) rowsum[t] = 0.f;

    const __nv_bfloat16* fb  = (const __nv_bfloat16*)g_fb  + (size_t)b * 32 * 1024;
    const __nv_bfloat16* gbp = (const __nv_bfloat16*)g_gb  + (size_t)b * 32 * 4096;
    const __nv_bfloat16* hhb = (const __nv_bfloat16*)g_hh2 + (size_t)b * 1024 * 128;

    const int fr = t >> 3, fseg = (t & 7) * 8;                 // 32 rows x 8 chunks
    cpa16(&Bsg[fr * 72 + fseg], &gbp[fr * 4096 + m0 + fseg]);
    cpa16(&F[fr * 72 + fseg], &fb[fr * 1024 + fseg]);
#pragma unroll
    for (int p = 0; p < 4; p++) {
        int slot = t + p * 256, hr = slot >> 4, hseg = (slot & 15) * 8;
        cpa16(&H[hr * 136 + hseg], &hhb[hr * 128 + hseg]);
    }
    cp_commit();

    float acc_s[2][2][4] = {};
    float acc_o[4][2][4] = {};
    float esum[2][2] = {};

    for (int nt = 0; nt < 16; nt++) {
        cp_wait<0>();
        __syncthreads();
        if (nt < 15) {
            const int bn = (nt + 1) & 1;
            cpa16(&F[bn * 2304 + fr * 72 + fseg], &fb[fr * 1024 + (nt + 1) * 64 + fseg]);
#pragma unroll
            for (int p = 0; p < 4; p++) {
                int slot = t + p * 256, hr = slot >> 4, hseg = (slot & 15) * 8;
                cpa16(&H[bn * 8704 + hr * 136 + hseg],
                      &hhb[(size_t)((nt + 1) * 64 + hr) * 128 + hseg]);
            }
            cp_commit();
        }
        const __nv_bfloat16* Fc = F + (nt & 1) * 2304;
        const __nv_bfloat16* Hc = H + (nt & 1) * 8704;
        mma_ktile<2, 2, 72, 72>(Fc, Bsg, mBaseS, nBaseS, lane, acc_s);
#pragma unroll
        for (int i = 0; i < 2; i++) {
            int row = mBaseS + i * 16 + g;
#pragma unroll
            for (int j = 0; j < 2; j++) {
                int col = nBaseS + j * 8 + 2 * tig;
                float e0 = ex2f(acc_s[i][j][0]);
                float e1 = ex2f(acc_s[i][j][1]);
                float e2 = ex2f(acc_s[i][j][2]);
                float e3 = ex2f(acc_s[i][j][3]);
                esum[j][0] += e0 + e2;
                esum[j][1] += e1 + e3;
                *(unsigned*)&P[row * 72 + col]       = packbf(e0, e1);
                *(unsigned*)&P[(row + 8) * 72 + col] = packbf(e2, e3);
                acc_s[i][j][0] = 0.f; acc_s[i][j][1] = 0.f;
                acc_s[i][j][2] = 0.f; acc_s[i][j][3] = 0.f;
            }
        }
        __syncthreads();
        mma_ktile<4, 2, 136, 72>(Hc,            P,           mBaseO, nBaseO, lane, acc_o);
        mma_ktile<4, 2, 136, 72>(Hc + 32 * 136, P + 32 * 72, mBaseO, nBaseO, lane, acc_o);
    }
#pragma unroll
    for (int j = 0; j < 2; j++) {
        int col = nBaseO + j * 8 + 2 * tig;
        atomicAdd(&rowsum[col],     esum[j][0]);
        atomicAdd(&rowsum[col + 1], esum[j][1]);
    }
    __syncthreads();
    // normalize o -> Po[c 128][m 64+8] bf16 (overwrites Bsg/F area — both dead)
#pragma unroll
    for (int j = 0; j < 2; j++) {
        int col = nBaseO + j * 8 + 2 * tig;
        float inv0 = 1.f / rowsum[col], inv1 = 1.f / rowsum[col + 1];
#pragma unroll
        for (int i = 0; i < 4; i++) {
            int c = mBaseO + i * 16 + g;
            *(unsigned*)&Po[c * 72 + col] =
                packbf(acc_o[i][j][0] * inv0, acc_o[i][j][1] * inv1);
            *(unsigned*)&Po[(c + 8) * 72 + col] =
                packbf(acc_o[i][j][2] * inv0, acc_o[i][j][3] * inv1);
        }
    }
    // stage w4 tile for step 0 (ocHalf=0, kt=0)
    const __nv_bfloat16* w4b = (const __nv_bfloat16*)g_w4b;
    const int br = t >> 4, bseg = (t & 15) * 8;   // 32 rows x 16 chunks? (16 segs of 8hw=128hw)
#pragma unroll
    for (int p = 0; p < 2; p++) {
        int slot = t + p * 256, r = slot >> 4, sg = (slot & 15) * 8;
        cpa16(&Wst[r * 136 + sg], &w4b[r * 256 + sg]);
    }
    cp_commit();
    __syncthreads();                               // Po visible to all

    // final GEMM: 2 ocHalves x 4 ktiles, double-buffered w4 staging
    for (int oh = 0; oh < 2; oh++) {
        float acc_f[4][2][4] = {};
#pragma unroll
        for (int kt = 0; kt < 4; kt++) {
            int s = oh * 4 + kt;
            cp_wait<0>();
            __syncthreads();
            if (s < 7) {
                int ns = s + 1;
                int nkt = ns & 3, noh = ns >> 2;
                const int bn = ns & 1;
#pragma unroll
                for (int p = 0; p < 2; p++) {
                    int slot = t + p * 256, r = slot >> 4, sg = (slot & 15) * 8;
                    cpa16(&Wst[bn * 4352 + r * 136 + sg],
                          &w4b[(nkt * 32 + r) * 256 + noh * 128 + sg]);
                }
                cp_commit();
            }
            mma_ktile<4, 2, 136, 72>(Wst + (s & 1) * 4352, Po + kt * 32 * 72,
                                     mBaseO, nBaseO, lane, acc_f);
        }
        // epilogue: + gbeta4 + x
#pragma unroll
        for (int i = 0; i < 4; i++) {
#pragma unroll
            for (int half = 0; half < 2; half++) {
                int r = oh * 128 + mBaseO + i * 16 + g + half * 8;
                float gb = g_ab4[256 + r];
                size_t base = ((size_t)(b * 256 + r) << 12) + m0;
#pragma unroll
                for (int j = 0; j < 2; j++) {
                    int col = nBaseO + j * 8 + 2 * tig;
                    float2 xv = *(const float2*)&x[base + col];
                    float2 o;
                    o.x = acc_f[i][j][half * 2 + 0] + gb + xv.x;
                    o.y = acc_f[i][j][half * 2 + 1] + gb + xv.y;
                    *(float2*)&out[base + col] = o;
                }
            }
        }
    }
}

// =====================================================================
extern "C" void kernel_launch(void* const* d_in, const int* in_sizes, int n_in,
                              void* d_out, int out_size)
{
    const float* x  = (const float*)d_in[0];
    const float* w1 = (const float*)d_in[1],  *b1 = (const float*)d_in[2],
               * s1 = (const float*)d_in[3],  *t1 = (const float*)d_in[4],
               * m1 = (const float*)d_in[5],  *v1 = (const float*)d_in[6];
    const float* w2 = (const float*)d_in[7],  *b2 = (const float*)d_in[8],
               * s2 = (const float*)d_in[9],  *t2 = (const float*)d_in[10],
               * m2 = (const float*)d_in[11], *v2 = (const float*)d_in[12];
    const float* w3 = (const float*)d_in[13], *b3 = (const float*)d_in[14],
               * s3 = (const float*)d_in[15], *t3 = (const float*)d_in[16],
               * m3 = (const float*)d_in[17], *v3 = (const float*)d_in[18];
    const float* w4 = (const float*)d_in[19], *b4 = (const float*)d_in[20],
               * s4 = (const float*)d_in[21], *t4 = (const float*)d_in[22],
               * m4 = (const float*)d_in[23], *v4 = (const float*)d_in[24];
    const float* gamma = (const float*)d_in[25];
    float* out = (float*)d_out;

    cudaFuncSetAttribute(fused_attn_kernel,
                         cudaFuncAttributeMaxDynamicSharedMemorySize, 59392);

    pre_kernel<<<162, 256>>>(w1, w2, w3, w4,
                             b1, s1, t1, m1, v1,
                             b2, s2, t2, m2, v2,
                             b3, s3, t3, m3, v3,
                             b4, s4, t4, m4, v4, gamma);

    proj_pool_kernel<<<dim3(32, 3, NB), 256>>>(x);

    fused_attn_kernel<<<dim3(64, NB), 256, 58112>>>(x, out);
}